// round 2
// baseline (speedup 1.0000x reference)
#include <cuda_runtime.h>
#include <math.h>

#define NN 8192
#define PP 128
#define DD 256
#define GCOLS 384   // P + D columns of M = [P | Xn]

// Scratch (device globals — no allocation allowed in kernel_launch)
__device__ float  g_xn[NN * DD];            // normalized embeddings, 8 MB
__device__ float  g_G[GCOLS * GCOLS];       // Gram matrix MᵀM, 576 KB
__device__ double g_acc[3];                 // 0: coherence frob sum, 1: structure SSE, 2: weight SSE

// ---------------------------------------------------------------------------
__device__ __forceinline__ float block_reduce_sum(float v) {
    __shared__ float red[8];
    int lane = threadIdx.x & 31;
    int wid  = threadIdx.x >> 5;
    #pragma unroll
    for (int o = 16; o > 0; o >>= 1) v += __shfl_xor_sync(0xffffffffu, v, o);
    if (lane == 0) red[wid] = v;
    __syncthreads();
    if (wid == 0) {
        v = (lane < ((int)blockDim.x >> 5)) ? red[lane] : 0.0f;
        #pragma unroll
        for (int o = 4; o > 0; o >>= 1) v += __shfl_xor_sync(0xffffffffu, v, o);
    }
    return v;  // valid in thread 0
}

// ---------------------------------------------------------------------------
__global__ void k_zero() {
    int i = blockIdx.x * blockDim.x + threadIdx.x;
    if (i < GCOLS * GCOLS) g_G[i] = 0.0f;
    if (i < 3) g_acc[i] = 0.0;
}

// One block (256 threads) per embedding row: xn = x / max(||x||, 1e-8)
__global__ void k_normalize(const float* __restrict__ X) {
    int row = blockIdx.x;
    int t   = threadIdx.x;
    float x = X[(size_t)row * DD + t];
    float ss = block_reduce_sum(x * x);
    __shared__ float s_inv;
    if (t == 0) s_inv = 1.0f / fmaxf(sqrtf(ss), 1e-8f);
    __syncthreads();
    g_xn[(size_t)row * DD + t] = x * s_inv;
}

// weight_loss SSE: sum (P - W)^2
__global__ void k_weight(const float* __restrict__ Pr, const float* __restrict__ W) {
    float s = 0.0f;
    int stride = gridDim.x * blockDim.x;
    for (int i = blockIdx.x * blockDim.x + threadIdx.x; i < NN * PP; i += stride) {
        float d = Pr[i] - W[i];
        s += d * d;
    }
    s = block_reduce_sum(s);
    if (threadIdx.x == 0) atomicAdd(&g_acc[2], (double)s);
}

// ---------------------------------------------------------------------------
// Gram kernel: G = MᵀM, M = [P | Xn] : [8192, 384]. 128x128 tiles (3x3),
// split-K by 16 (512 K per block) -> grid (9,16) = 144 blocks ~ 1 wave.
// Each 256-thread block: 8x8 micro-tile per thread, BK=32 smem staging.
#define GK 512
__global__ void k_gram(const float* __restrict__ Pr) {
    __shared__ float Ur[32][128];
    __shared__ float Vc[32][128];

    int tile = blockIdx.x;            // 0..8
    int rb = tile / 3, cb = tile % 3;
    int k0 = blockIdx.y * GK;

    // tile index -> source array: 0 = P cols 0..127, 1 = Xn cols 0..127, 2 = Xn cols 128..255
    const float* srcR = (rb == 0) ? Pr : (const float*)g_xn;
    const float* srcC = (cb == 0) ? Pr : (const float*)g_xn;
    int ldR = (rb == 0) ? PP : DD;
    int ldC = (cb == 0) ? PP : DD;
    int offR = (rb == 2) ? 128 : 0;
    int offC = (cb == 2) ? 128 : 0;

    int tid = threadIdx.x;
    int tx = tid & 15, ty = tid >> 4;
    int lk = tid >> 3;              // 0..31  (K row within tile)
    int lc = (tid & 7) * 16;        // 0..112 (col within tile)

    float acc[8][8] = {};

    for (int kk = 0; kk < GK; kk += 32) {
        #pragma unroll
        for (int q = 0; q < 4; q++) {
            *(float4*)&Ur[lk][lc + 4 * q] =
                *(const float4*)&srcR[(size_t)(k0 + kk + lk) * ldR + offR + lc + 4 * q];
            *(float4*)&Vc[lk][lc + 4 * q] =
                *(const float4*)&srcC[(size_t)(k0 + kk + lk) * ldC + offC + lc + 4 * q];
        }
        __syncthreads();
        #pragma unroll
        for (int k = 0; k < 32; k++) {
            float4 u0 = *(float4*)&Ur[k][ty * 8];
            float4 u1 = *(float4*)&Ur[k][ty * 8 + 4];
            float4 v0 = *(float4*)&Vc[k][tx * 8];
            float4 v1 = *(float4*)&Vc[k][tx * 8 + 4];
            float u[8] = {u0.x, u0.y, u0.z, u0.w, u1.x, u1.y, u1.z, u1.w};
            float v[8] = {v0.x, v0.y, v0.z, v0.w, v1.x, v1.y, v1.z, v1.w};
            #pragma unroll
            for (int i = 0; i < 8; i++)
                #pragma unroll
                for (int j = 0; j < 8; j++)
                    acc[i][j] += u[i] * v[j];
        }
        __syncthreads();
    }

    int r0 = rb * 128 + ty * 8;
    int c0 = cb * 128 + tx * 8;
    #pragma unroll
    for (int i = 0; i < 8; i++)
        #pragma unroll
        for (int j = 0; j < 8; j++)
            atomicAdd(&g_G[(r0 + i) * GCOLS + c0 + j], acc[i][j]);
}

// coherence * N^2 = sum_{r,c} w_r w_c G_rc^2, w = +1 for first 128 cols (P), -1 otherwise
__global__ void k_coh() {
    float s = 0.0f;
    int stride = gridDim.x * blockDim.x;
    for (int i = blockIdx.x * blockDim.x + threadIdx.x; i < GCOLS * GCOLS; i += stride) {
        int r = i / GCOLS, c = i % GCOLS;
        float g = g_G[i];
        float sgn = ((r < 128) == (c < 128)) ? 1.0f : -1.0f;
        s += sgn * g * g;
    }
    s = block_reduce_sum(s);
    if (threadIdx.x == 0) atomicAdd(&g_acc[0], (double)s);
}

// ---------------------------------------------------------------------------
// Structure kernel: fused S = A @ P and SSE of (P - S).
// BM=64 rows/block (grid 128), BN=128 (full P width), BK=32.
// 256 threads, 4x8 outputs per thread. A (256 MB) read exactly once.
__global__ void k_structure(const float* __restrict__ A, const float* __restrict__ Pr) {
    __shared__ float As[32][64];    // transposed: As[k][m]
    __shared__ float Bs[32][128];   // Bs[k][c]

    int tid = threadIdx.x;
    int tx = tid & 15, ty = tid >> 4;
    int m_base = blockIdx.x * 64;

    int lm = tid >> 2;              // 0..63  (A row within tile)
    int lk = (tid & 3) * 8;         // 0,8,16,24
    int pk = tid >> 3;              // 0..31  (P K-row)
    int pc = (tid & 7) * 16;        // 0..112

    float acc[4][8] = {};

    for (int k0 = 0; k0 < NN; k0 += 32) {
        float4 a0 = *(const float4*)&A[(size_t)(m_base + lm) * NN + k0 + lk];
        float4 a1 = *(const float4*)&A[(size_t)(m_base + lm) * NN + k0 + lk + 4];
        As[lk + 0][lm] = a0.x; As[lk + 1][lm] = a0.y;
        As[lk + 2][lm] = a0.z; As[lk + 3][lm] = a0.w;
        As[lk + 4][lm] = a1.x; As[lk + 5][lm] = a1.y;
        As[lk + 6][lm] = a1.z; As[lk + 7][lm] = a1.w;
        #pragma unroll
        for (int q = 0; q < 4; q++)
            *(float4*)&Bs[pk][pc + 4 * q] =
                *(const float4*)&Pr[(size_t)(k0 + pk) * PP + pc + 4 * q];
        __syncthreads();
        #pragma unroll
        for (int k = 0; k < 32; k++) {
            float4 av = *(float4*)&As[k][ty * 4];
            float4 b0 = *(float4*)&Bs[k][tx * 8];
            float4 b1 = *(float4*)&Bs[k][tx * 8 + 4];
            float a[4] = {av.x, av.y, av.z, av.w};
            float b[8] = {b0.x, b0.y, b0.z, b0.w, b1.x, b1.y, b1.z, b1.w};
            #pragma unroll
            for (int i = 0; i < 4; i++)
                #pragma unroll
                for (int j = 0; j < 8; j++)
                    acc[i][j] += a[i] * b[j];
        }
        __syncthreads();
    }

    // fused loss epilogue: sum (P[m][c] - S[m][c])^2
    float s = 0.0f;
    #pragma unroll
    for (int i = 0; i < 4; i++) {
        int m = m_base + ty * 4 + i;
        #pragma unroll
        for (int j = 0; j < 8; j++) {
            float d = Pr[(size_t)m * PP + tx * 8 + j] - acc[i][j];
            s += d * d;
        }
    }
    s = block_reduce_sum(s);
    if (tid == 0) atomicAdd(&g_acc[1], (double)s);
}

// ---------------------------------------------------------------------------
__global__ void k_final(float* __restrict__ out) {
    double nn = (double)NN * (double)NN;
    double np = (double)NN * (double)PP;
    out[0] = (float)(g_acc[0] / nn + g_acc[1] / np + g_acc[2] / np);
}

// ---------------------------------------------------------------------------
extern "C" void kernel_launch(void* const* d_in, const int* in_sizes, int n_in,
                              void* d_out, int out_size) {
    const float* preds = (const float*)d_in[0];   // [8192, 128]
    const float* emb   = (const float*)d_in[1];   // [8192, 256]
    const float* adj   = (const float*)d_in[2];   // [8192, 8192]
    const float* wts   = (const float*)d_in[3];   // [8192, 128]
    float* out = (float*)d_out;

    k_zero<<<(GCOLS * GCOLS + 255) / 256, 256>>>();
    k_normalize<<<NN, DD>>>(emb);
    k_weight<<<256, 256>>>(preds, wts);
    k_gram<<<dim3(9, 16), 256>>>(preds);
    k_coh<<<144, 256>>>();
    k_structure<<<NN / 64, 256>>>(adj, preds);
    k_final<<<1, 1>>>(out);
}

// round 4
// speedup vs baseline: 4.4666x; 4.4666x over previous
#include <cuda_runtime.h>
#include <cuda_bf16.h>
#include <math.h>
#include <stdint.h>

#define NN 8192
#define PP 128
#define DD 256
#define GCOLS 384

// ---------------- device scratch (static globals — no runtime alloc) ----------
__device__ float  g_xn[NN * DD];                    // normalized embeddings (8 MB)
__device__ float  g_G[GCOLS * GCOLS];               // Gram matrix
__device__ double g_acc[3];                         // 0: coherence, 1: structure, 2: weight
__device__ __nv_bfloat16 g_Pt[(size_t)PP * NN];     // P transposed, bf16 (2 MB)

// ---------------------------------------------------------------------------
__device__ __forceinline__ uint32_t smem_u32(const void* p) {
    return (uint32_t)__cvta_generic_to_shared(p);
}

__device__ __forceinline__ float block_reduce_sum(float v) {
    __shared__ float red[8];
    int lane = threadIdx.x & 31;
    int wid  = threadIdx.x >> 5;
    #pragma unroll
    for (int o = 16; o > 0; o >>= 1) v += __shfl_xor_sync(0xffffffffu, v, o);
    if (lane == 0) red[wid] = v;
    __syncthreads();
    if (wid == 0) {
        v = (lane < ((int)blockDim.x >> 5)) ? red[lane] : 0.0f;
        #pragma unroll
        for (int o = 4; o > 0; o >>= 1) v += __shfl_xor_sync(0xffffffffu, v, o);
    }
    return v;
}

__global__ void k_zero() {
    int i = blockIdx.x * blockDim.x + threadIdx.x;
    if (i < GCOLS * GCOLS) g_G[i] = 0.0f;
    if (i < 3) g_acc[i] = 0.0;
}

__global__ void k_normalize(const float* __restrict__ X) {
    int row = blockIdx.x;
    int t   = threadIdx.x;
    float x = X[(size_t)row * DD + t];
    float ss = block_reduce_sum(x * x);
    __shared__ float s_inv;
    if (t == 0) s_inv = 1.0f / fmaxf(sqrtf(ss), 1e-8f);
    __syncthreads();
    g_xn[(size_t)row * DD + t] = x * s_inv;
}

__global__ void k_weight(const float* __restrict__ Pr, const float* __restrict__ W) {
    float s = 0.0f;
    int stride = gridDim.x * blockDim.x;
    for (int i = blockIdx.x * blockDim.x + threadIdx.x; i < NN * PP; i += stride) {
        float d = Pr[i] - W[i];
        s += d * d;
    }
    s = block_reduce_sum(s);
    if (threadIdx.x == 0) atomicAdd(&g_acc[2], (double)s);
}

// P [8192,128] fp32 -> Pt [128,8192] bf16 (smem tile transpose)
__global__ void k_convPt(const float* __restrict__ P) {
    __shared__ float t[32][33];
    int kb = blockIdx.x * 32;
    int nb = blockIdx.y * 32;
    int tx = threadIdx.x & 31, ty = threadIdx.x >> 5;   // 256 threads: ty 0..7
    #pragma unroll
    for (int r = ty; r < 32; r += 8)
        t[r][tx] = P[(size_t)(kb + r) * PP + nb + tx];
    __syncthreads();
    #pragma unroll
    for (int r = ty; r < 32; r += 8)
        g_Pt[(size_t)(nb + r) * NN + kb + tx] = __float2bfloat16(t[tx][r]);
}

// ---------------------------------------------------------------------------
// Gram kernel: G = MᵀM, M = [P | Xn] : [8192, 384] (fp32)
#define GK 512
__global__ void k_gram(const float* __restrict__ Pr) {
    __shared__ float Ur[32][128];
    __shared__ float Vc[32][128];

    int tile = blockIdx.x;
    int rb = tile / 3, cb = tile % 3;
    int k0 = blockIdx.y * GK;

    const float* srcR = (rb == 0) ? Pr : (const float*)g_xn;
    const float* srcC = (cb == 0) ? Pr : (const float*)g_xn;
    int ldR = (rb == 0) ? PP : DD;
    int ldC = (cb == 0) ? PP : DD;
    int offR = (rb == 2) ? 128 : 0;
    int offC = (cb == 2) ? 128 : 0;

    int tid = threadIdx.x;
    int tx = tid & 15, ty = tid >> 4;
    int lk = tid >> 3;
    int lc = (tid & 7) * 16;

    float acc[8][8] = {};

    for (int kk = 0; kk < GK; kk += 32) {
        #pragma unroll
        for (int q = 0; q < 4; q++) {
            *(float4*)&Ur[lk][lc + 4 * q] =
                *(const float4*)&srcR[(size_t)(k0 + kk + lk) * ldR + offR + lc + 4 * q];
            *(float4*)&Vc[lk][lc + 4 * q] =
                *(const float4*)&srcC[(size_t)(k0 + kk + lk) * ldC + offC + lc + 4 * q];
        }
        __syncthreads();
        #pragma unroll
        for (int k = 0; k < 32; k++) {
            float4 u0 = *(float4*)&Ur[k][ty * 8];
            float4 u1 = *(float4*)&Ur[k][ty * 8 + 4];
            float4 v0 = *(float4*)&Vc[k][tx * 8];
            float4 v1 = *(float4*)&Vc[k][tx * 8 + 4];
            float u[8] = {u0.x, u0.y, u0.z, u0.w, u1.x, u1.y, u1.z, u1.w};
            float v[8] = {v0.x, v0.y, v0.z, v0.w, v1.x, v1.y, v1.z, v1.w};
            #pragma unroll
            for (int i = 0; i < 8; i++)
                #pragma unroll
                for (int j = 0; j < 8; j++)
                    acc[i][j] += u[i] * v[j];
        }
        __syncthreads();
    }

    int r0 = rb * 128 + ty * 8;
    int c0 = cb * 128 + tx * 8;
    #pragma unroll
    for (int i = 0; i < 8; i++)
        #pragma unroll
        for (int j = 0; j < 8; j++)
            atomicAdd(&g_G[(r0 + i) * GCOLS + c0 + j], acc[i][j]);
}

__global__ void k_coh() {
    float s = 0.0f;
    int stride = gridDim.x * blockDim.x;
    for (int i = blockIdx.x * blockDim.x + threadIdx.x; i < GCOLS * GCOLS; i += stride) {
        int r = i / GCOLS, c = i % GCOLS;
        float g = g_G[i];
        float sgn = ((r < 128) == (c < 128)) ? 1.0f : -1.0f;
        s += sgn * g * g;
    }
    s = block_reduce_sum(s);
    if (threadIdx.x == 0) atomicAdd(&g_acc[0], (double)s);
}

// ---------------------------------------------------------------------------
// Structure: S = A @ P via mma.sync bf16 HMMA, fused fp32->bf16 of A and SSE
// epilogue. BM=64, BN=128, KT=64. Grid 128 CTAs x 256 threads (8 warps 4x2).
// Warp tile 16m x 64n, m16n8k16 fragments, 32 fp32 accums/thread.
#define KT 64
#define APAD 72          // bf16 row stride (144B): conflict-free ldmatrix

__device__ __forceinline__ void ldmx4(uint32_t& r0, uint32_t& r1, uint32_t& r2,
                                      uint32_t& r3, uint32_t addr) {
    asm volatile("ldmatrix.sync.aligned.m8n8.x4.shared.b16 {%0,%1,%2,%3}, [%4];"
                 : "=r"(r0), "=r"(r1), "=r"(r2), "=r"(r3) : "r"(addr));
}
__device__ __forceinline__ void mma_bf16(float* c, uint32_t a0, uint32_t a1,
                                         uint32_t a2, uint32_t a3,
                                         uint32_t b0, uint32_t b1) {
    asm volatile(
        "mma.sync.aligned.m16n8k16.row.col.f32.bf16.bf16.f32 "
        "{%0,%1,%2,%3}, {%4,%5,%6,%7}, {%8,%9}, {%0,%1,%2,%3};"
        : "+f"(c[0]), "+f"(c[1]), "+f"(c[2]), "+f"(c[3])
        : "r"(a0), "r"(a1), "r"(a2), "r"(a3), "r"(b0), "r"(b1));
}

__global__ void __launch_bounds__(256) k_structure_mma(const float* __restrict__ A,
                                                       const float* __restrict__ Pr) {
    __shared__ __nv_bfloat16 sA[64 * APAD];
    __shared__ __nv_bfloat16 sB[128 * APAD];

    int tid  = threadIdx.x;
    int wid  = tid >> 5;
    int lane = tid & 31;
    int gid  = lane >> 2;          // 0..7
    int tid4 = lane & 3;           // 0..3
    int wm   = wid >> 1;           // 0..3 : 16-row slice
    int wn   = wid & 1;            // 0..1 : 64-col slice
    int m_base = blockIdx.x * 64;

    // ldmatrix per-lane row/col within a 16x16 x4 footprint
    int lrow = (lane & 7) + ((lane >> 3) & 1) * 8;   // 0..15
    int lk8  = (lane >> 4) * 8;                      // 0 or 8

    uint32_t sA_u = smem_u32(sA);
    uint32_t sB_u = smem_u32(sB);

    // staging registers
    float4 rA[4];
    uint4  rB[4];

    // gmem load helper indices
    // A: chunk c = tid + q*256 : row = c>>4 (0..63), col16 = c&15 (4 floats each)
    // B: chunk c = tid + q*256 : row = c>>3 (0..127), col16 = c&7 (8 bf16 each)

    // preload iter 0
    {
        int k0 = 0;
        #pragma unroll
        for (int q = 0; q < 4; q++) {
            int c = tid + q * 256;
            rA[q] = *(const float4*)&A[(size_t)(m_base + (c >> 4)) * NN + k0 + (c & 15) * 4];
            int cb = tid + q * 256;
            rB[q] = *(const uint4*)&g_Pt[(size_t)(cb >> 3) * NN + k0 + (cb & 7) * 8];
        }
    }

    float acc[8][4] = {};

    const int NIT = NN / KT;   // 128
    for (int it = 0; it < NIT; it++) {
        // store staged tile to smem (A converted to bf16)
        #pragma unroll
        for (int q = 0; q < 4; q++) {
            int c = tid + q * 256;
            __nv_bfloat162 lo = __floats2bfloat162_rn(rA[q].x, rA[q].y);
            __nv_bfloat162 hi = __floats2bfloat162_rn(rA[q].z, rA[q].w);
            uint2 o; o.x = *(uint32_t*)&lo; o.y = *(uint32_t*)&hi;
            *(uint2*)&sA[(c >> 4) * APAD + (c & 15) * 4] = o;
            *(uint4*)&sB[(c >> 3) * APAD + (c & 7) * 8] = rB[q];
        }
        __syncthreads();

        // issue next tile's gmem loads (consumed next iteration)
        if (it + 1 < NIT) {
            int k0 = (it + 1) * KT;
            #pragma unroll
            for (int q = 0; q < 4; q++) {
                int c = tid + q * 256;
                rA[q] = *(const float4*)&A[(size_t)(m_base + (c >> 4)) * NN + k0 + (c & 15) * 4];
                rB[q] = *(const uint4*)&g_Pt[(size_t)(c >> 3) * NN + k0 + (c & 7) * 8];
            }
        }

        // compute KT=64 in four k16 steps
        #pragma unroll
        for (int kk = 0; kk < KT; kk += 16) {
            uint32_t a0, a1, a2, a3;
            ldmx4(a0, a1, a2, a3,
                  sA_u + ((wm * 16 + lrow) * APAD + kk + lk8) * 2);
            #pragma unroll
            for (int bt = 0; bt < 4; bt++) {
                uint32_t b0, b1, b2, b3;
                ldmx4(b0, b1, b2, b3,
                      sB_u + ((wn * 64 + bt * 16 + lrow) * APAD + kk + lk8) * 2);
                mma_bf16(acc[bt * 2 + 0], a0, a1, a2, a3, b0, b2);
                mma_bf16(acc[bt * 2 + 1], a0, a1, a2, a3, b1, b3);
            }
        }
        __syncthreads();
    }

    // fused SSE epilogue: sum (P[m][c] - S[m][c])^2
    float s = 0.0f;
    #pragma unroll
    for (int nt = 0; nt < 8; nt++) {
        int col = wn * 64 + nt * 8 + tid4 * 2;
        int m0 = m_base + wm * 16 + gid;
        float p00 = Pr[(size_t)m0 * PP + col];
        float p01 = Pr[(size_t)m0 * PP + col + 1];
        float p10 = Pr[(size_t)(m0 + 8) * PP + col];
        float p11 = Pr[(size_t)(m0 + 8) * PP + col + 1];
        float d0 = p00 - acc[nt][0];
        float d1 = p01 - acc[nt][1];
        float d2 = p10 - acc[nt][2];
        float d3 = p11 - acc[nt][3];
        s += d0 * d0 + d1 * d1 + d2 * d2 + d3 * d3;
    }
    s = block_reduce_sum(s);
    if (tid == 0) atomicAdd(&g_acc[1], (double)s);
}

// ---------------------------------------------------------------------------
__global__ void k_final(float* __restrict__ out) {
    double nn = (double)NN * (double)NN;
    double np = (double)NN * (double)PP;
    out[0] = (float)(g_acc[0] / nn + g_acc[1] / np + g_acc[2] / np);
}

// ---------------------------------------------------------------------------
extern "C" void kernel_launch(void* const* d_in, const int* in_sizes, int n_in,
                              void* d_out, int out_size) {
    const float* preds = (const float*)d_in[0];   // [8192, 128]
    const float* emb   = (const float*)d_in[1];   // [8192, 256]
    const float* adj   = (const float*)d_in[2];   // [8192, 8192]
    const float* wts   = (const float*)d_in[3];   // [8192, 128]
    float* out = (float*)d_out;

    k_zero<<<(GCOLS * GCOLS + 255) / 256, 256>>>();
    k_normalize<<<NN, DD>>>(emb);
    k_weight<<<256, 256>>>(preds, wts);
    k_convPt<<<dim3(NN / 32, PP / 32), 256>>>(preds);
    k_gram<<<dim3(9, 16), 256>>>(preds);
    k_coh<<<144, 256>>>();
    k_structure_mma<<<NN / 64, 256>>>(adj, preds);
    k_final<<<1, 1>>>(out);
}

// round 5
// speedup vs baseline: 4.5177x; 1.0114x over previous
#include <cuda_runtime.h>
#include <cuda_bf16.h>
#include <math.h>
#include <stdint.h>

#define NN 8192
#define PP 128
#define DD 256
#define GCOLS 384

// ---------------- device scratch (static globals — no runtime alloc) ----------
__device__ float  g_xn[NN * DD];                    // normalized embeddings (8 MB)
__device__ float  g_G[GCOLS * GCOLS];               // Gram matrix
__device__ double g_acc[3];                         // 0: coherence, 1: structure, 2: (unused)
__device__ double g_accW[32];                       // weight-loss per-block partials
__device__ __nv_bfloat16 g_Pt[(size_t)PP * NN];     // P transposed, bf16 (2 MB)

// ---------------------------------------------------------------------------
__device__ __forceinline__ uint32_t smem_u32(const void* p) {
    return (uint32_t)__cvta_generic_to_shared(p);
}

__device__ __forceinline__ float block_reduce_sum(float v) {
    __shared__ float red[8];
    int lane = threadIdx.x & 31;
    int wid  = threadIdx.x >> 5;
    #pragma unroll
    for (int o = 16; o > 0; o >>= 1) v += __shfl_xor_sync(0xffffffffu, v, o);
    if (lane == 0) red[wid] = v;
    __syncthreads();
    if (wid == 0) {
        v = (lane < ((int)blockDim.x >> 5)) ? red[lane] : 0.0f;
        #pragma unroll
        for (int o = 4; o > 0; o >>= 1) v += __shfl_xor_sync(0xffffffffu, v, o);
    }
    return v;
}

// ---------------------------------------------------------------------------
// PREP (fused): normalize | convPt | weight partials | zero G/acc
//   [0, 8192)            normalize row b
//   [8192, 9216)         convPt tile
//   [9216, 9248)         weight partial -> g_accW
//   [9248, 9824)         zero g_G / g_acc
#define PREP_NORM   8192
#define PREP_CONV   (PREP_NORM + 1024)
#define PREP_WEIGHT (PREP_CONV + 32)
#define PREP_ZERO   (PREP_WEIGHT + 576)

__global__ void k_prep(const float* __restrict__ X, const float* __restrict__ P,
                       const float* __restrict__ Pr, const float* __restrict__ W) {
    int b = blockIdx.x;
    int t = threadIdx.x;

    if (b < PREP_NORM) {
        // normalize: one embedding row per block
        float x = X[(size_t)b * DD + t];
        float ss = block_reduce_sum(x * x);
        __shared__ float s_inv;
        if (t == 0) s_inv = 1.0f / fmaxf(sqrtf(ss), 1e-8f);
        __syncthreads();
        g_xn[(size_t)b * DD + t] = x * s_inv;
    } else if (b < PREP_CONV) {
        // P [8192,128] fp32 -> Pt [128,8192] bf16 (smem tile transpose)
        int b2 = b - PREP_NORM;
        __shared__ float tt[32][33];
        int kb = (b2 >> 2) * 32;
        int nb = (b2 & 3) * 32;
        int tx = t & 31, ty = t >> 5;
        #pragma unroll
        for (int r = ty; r < 32; r += 8)
            tt[r][tx] = P[(size_t)(kb + r) * PP + nb + tx];
        __syncthreads();
        #pragma unroll
        for (int r = ty; r < 32; r += 8)
            g_Pt[(size_t)(nb + r) * NN + kb + tx] = __float2bfloat16(tt[tx][r]);
    } else if (b < PREP_WEIGHT) {
        // weight partial SSE into dedicated slot (no atomics -> no zero race)
        int b2 = b - PREP_CONV;
        float s = 0.0f;
        int stride = 32 * 256;
        for (int i = b2 * 256 + t; i < NN * PP; i += stride) {
            float d = Pr[i] - W[i];
            s += d * d;
        }
        s = block_reduce_sum(s);
        if (t == 0) g_accW[b2] = (double)s;
    } else {
        int i = (b - PREP_WEIGHT) * 256 + t;
        if (i < GCOLS * GCOLS) g_G[i] = 0.0f;
        if (i < 3) g_acc[i] = 0.0;
    }
}

// ---------------------------------------------------------------------------
// MAIN (fused): structure GEMM (tensor pipe) || gram GEMM (fma pipe)
#define STRUCT_BLOCKS 128
#define GRAM_SLICES 32
#define GK 256
#define GRAM_BLOCKS (9 * GRAM_SLICES)

#define KT 64
#define APAD 72

__device__ __forceinline__ void ldmx4(uint32_t& r0, uint32_t& r1, uint32_t& r2,
                                      uint32_t& r3, uint32_t addr) {
    asm volatile("ldmatrix.sync.aligned.m8n8.x4.shared.b16 {%0,%1,%2,%3}, [%4];"
                 : "=r"(r0), "=r"(r1), "=r"(r2), "=r"(r3) : "r"(addr));
}
__device__ __forceinline__ void mma_bf16(float* c, uint32_t a0, uint32_t a1,
                                         uint32_t a2, uint32_t a3,
                                         uint32_t b0, uint32_t b1) {
    asm volatile(
        "mma.sync.aligned.m16n8k16.row.col.f32.bf16.bf16.f32 "
        "{%0,%1,%2,%3}, {%4,%5,%6,%7}, {%8,%9}, {%0,%1,%2,%3};"
        : "+f"(c[0]), "+f"(c[1]), "+f"(c[2]), "+f"(c[3])
        : "r"(a0), "r"(a1), "r"(a2), "r"(a3), "r"(b0), "r"(b1));
}

// structure flavor: S = A @ P via bf16 HMMA, fused A fp32->bf16 and SSE epilogue
// BM=64, BN=128, KT=64; 8 warps 4x2; warp tile 16x64.
__device__ __forceinline__ void structure_body(const float* __restrict__ A,
                                               const float* __restrict__ Pr,
                                               char* sm, int bid) {
    __nv_bfloat16* sA = (__nv_bfloat16*)sm;                    // 64*APAD*2  = 9216 B
    __nv_bfloat16* sB = (__nv_bfloat16*)(sm + 64 * APAD * 2);  // 128*APAD*2 = 18432 B

    int tid  = threadIdx.x;
    int wid  = tid >> 5;
    int lane = tid & 31;
    int gid  = lane >> 2;
    int tid4 = lane & 3;
    int wm   = wid >> 1;
    int wn   = wid & 1;
    int m_base = bid * 64;

    int lrow = (lane & 7) + ((lane >> 3) & 1) * 8;
    int lk8  = (lane >> 4) * 8;

    uint32_t sA_u = smem_u32(sA);
    uint32_t sB_u = smem_u32(sB);

    float4 rA[4];
    uint4  rB[4];

    {
        #pragma unroll
        for (int q = 0; q < 4; q++) {
            int c = tid + q * 256;
            rA[q] = *(const float4*)&A[(size_t)(m_base + (c >> 4)) * NN + (c & 15) * 4];
            rB[q] = *(const uint4*)&g_Pt[(size_t)(c >> 3) * NN + (c & 7) * 8];
        }
    }

    float acc[8][4] = {};

    const int NIT = NN / KT;
    for (int it = 0; it < NIT; it++) {
        #pragma unroll
        for (int q = 0; q < 4; q++) {
            int c = tid + q * 256;
            __nv_bfloat162 lo = __floats2bfloat162_rn(rA[q].x, rA[q].y);
            __nv_bfloat162 hi = __floats2bfloat162_rn(rA[q].z, rA[q].w);
            uint2 o; o.x = *(uint32_t*)&lo; o.y = *(uint32_t*)&hi;
            *(uint2*)&sA[(c >> 4) * APAD + (c & 15) * 4] = o;
            *(uint4*)&sB[(c >> 3) * APAD + (c & 7) * 8] = rB[q];
        }
        __syncthreads();

        if (it + 1 < NIT) {
            int k0 = (it + 1) * KT;
            #pragma unroll
            for (int q = 0; q < 4; q++) {
                int c = tid + q * 256;
                rA[q] = *(const float4*)&A[(size_t)(m_base + (c >> 4)) * NN + k0 + (c & 15) * 4];
                rB[q] = *(const uint4*)&g_Pt[(size_t)(c >> 3) * NN + k0 + (c & 7) * 8];
            }
        }

        #pragma unroll
        for (int kk = 0; kk < KT; kk += 16) {
            uint32_t a0, a1, a2, a3;
            ldmx4(a0, a1, a2, a3,
                  sA_u + ((wm * 16 + lrow) * APAD + kk + lk8) * 2);
            #pragma unroll
            for (int bt = 0; bt < 4; bt++) {
                uint32_t b0, b1, b2, b3;
                ldmx4(b0, b1, b2, b3,
                      sB_u + ((wn * 64 + bt * 16 + lrow) * APAD + kk + lk8) * 2);
                mma_bf16(acc[bt * 2 + 0], a0, a1, a2, a3, b0, b2);
                mma_bf16(acc[bt * 2 + 1], a0, a1, a2, a3, b1, b3);
            }
        }
        __syncthreads();
    }

    float s = 0.0f;
    #pragma unroll
    for (int nt = 0; nt < 8; nt++) {
        int col = wn * 64 + nt * 8 + tid4 * 2;
        int m0 = m_base + wm * 16 + gid;
        float p00 = Pr[(size_t)m0 * PP + col];
        float p01 = Pr[(size_t)m0 * PP + col + 1];
        float p10 = Pr[(size_t)(m0 + 8) * PP + col];
        float p11 = Pr[(size_t)(m0 + 8) * PP + col + 1];
        float d0 = p00 - acc[nt][0];
        float d1 = p01 - acc[nt][1];
        float d2 = p10 - acc[nt][2];
        float d3 = p11 - acc[nt][3];
        s += d0 * d0 + d1 * d1 + d2 * d2 + d3 * d3;
    }
    s = block_reduce_sum(s);
    if (tid == 0) atomicAdd(&g_acc[1], (double)s);
}

// gram flavor: G = MᵀM, M = [P | Xn] : [8192, 384], fp32 FFMA, split-K 32
__device__ __forceinline__ void gram_body(const float* __restrict__ Pr,
                                          char* sm, int bid) {
    float (*Ur)[128] = (float(*)[128])sm;             // 16384 B
    float (*Vc)[128] = (float(*)[128])(sm + 16384);   // 16384 B

    int tile = bid % 9;
    int rb = tile / 3, cb = tile % 3;
    int k0 = (bid / 9) * GK;

    const float* srcR = (rb == 0) ? Pr : (const float*)g_xn;
    const float* srcC = (cb == 0) ? Pr : (const float*)g_xn;
    int ldR = (rb == 0) ? PP : DD;
    int ldC = (cb == 0) ? PP : DD;
    int offR = (rb == 2) ? 128 : 0;
    int offC = (cb == 2) ? 128 : 0;

    int tid = threadIdx.x;
    int tx = tid & 15, ty = tid >> 4;
    int lk = tid >> 3;
    int lc = (tid & 7) * 16;

    float acc[8][8] = {};

    for (int kk = 0; kk < GK; kk += 32) {
        #pragma unroll
        for (int q = 0; q < 4; q++) {
            *(float4*)&Ur[lk][lc + 4 * q] =
                *(const float4*)&srcR[(size_t)(k0 + kk + lk) * ldR + offR + lc + 4 * q];
            *(float4*)&Vc[lk][lc + 4 * q] =
                *(const float4*)&srcC[(size_t)(k0 + kk + lk) * ldC + offC + lc + 4 * q];
        }
        __syncthreads();
        #pragma unroll
        for (int k = 0; k < 32; k++) {
            float4 u0 = *(float4*)&Ur[k][ty * 8];
            float4 u1 = *(float4*)&Ur[k][ty * 8 + 4];
            float4 v0 = *(float4*)&Vc[k][tx * 8];
            float4 v1 = *(float4*)&Vc[k][tx * 8 + 4];
            float u[8] = {u0.x, u0.y, u0.z, u0.w, u1.x, u1.y, u1.z, u1.w};
            float v[8] = {v0.x, v0.y, v0.z, v0.w, v1.x, v1.y, v1.z, v1.w};
            #pragma unroll
            for (int i = 0; i < 8; i++)
                #pragma unroll
                for (int j = 0; j < 8; j++)
                    acc[i][j] += u[i] * v[j];
        }
        __syncthreads();
    }

    int r0 = rb * 128 + ty * 8;
    int c0 = cb * 128 + tx * 8;
    #pragma unroll
    for (int i = 0; i < 8; i++)
        #pragma unroll
        for (int j = 0; j < 8; j++)
            atomicAdd(&g_G[(r0 + i) * GCOLS + c0 + j], acc[i][j]);
}

__global__ void __launch_bounds__(256, 2) k_main(const float* __restrict__ A,
                                                 const float* __restrict__ Pr) {
    __shared__ __align__(16) char sm[32768];
    if (blockIdx.x < STRUCT_BLOCKS) {
        structure_body(A, Pr, sm, blockIdx.x);
    } else {
        gram_body(Pr, sm, blockIdx.x - STRUCT_BLOCKS);
    }
}

// ---------------------------------------------------------------------------
// coherence * N^2 = sum_{r,c} w_r w_c G_rc^2
__global__ void k_coh() {
    float s = 0.0f;
    int stride = gridDim.x * blockDim.x;
    for (int i = blockIdx.x * blockDim.x + threadIdx.x; i < GCOLS * GCOLS; i += stride) {
        int r = i / GCOLS, c = i % GCOLS;
        float g = g_G[i];
        float sgn = ((r < 128) == (c < 128)) ? 1.0f : -1.0f;
        s += sgn * g * g;
    }
    s = block_reduce_sum(s);
    if (threadIdx.x == 0) atomicAdd(&g_acc[0], (double)s);
}

__global__ void k_final(float* __restrict__ out) {
    double nn = (double)NN * (double)NN;
    double np = (double)NN * (double)PP;
    double w = 0.0;
    #pragma unroll
    for (int i = 0; i < 32; i++) w += g_accW[i];
    out[0] = (float)(g_acc[0] / nn + g_acc[1] / np + w / np);
}

// ---------------------------------------------------------------------------
extern "C" void kernel_launch(void* const* d_in, const int* in_sizes, int n_in,
                              void* d_out, int out_size) {
    const float* preds = (const float*)d_in[0];   // [8192, 128]
    const float* emb   = (const float*)d_in[1];   // [8192, 256]
    const float* adj   = (const float*)d_in[2];   // [8192, 8192]
    const float* wts   = (const float*)d_in[3];   // [8192, 128]
    float* out = (float*)d_out;

    k_prep<<<PREP_ZERO, 256>>>(emb, preds, preds, wts);
    k_main<<<STRUCT_BLOCKS + GRAM_BLOCKS, 256>>>(adj, preds);
    k_coh<<<144, 256>>>();
    k_final<<<1, 1>>>(out);
}

// round 6
// speedup vs baseline: 6.5725x; 1.4549x over previous
#include <cuda_runtime.h>
#include <cuda_bf16.h>
#include <math.h>
#include <stdint.h>

#define NN 8192
#define PP 128
#define DD 256

// ---------------- device scratch (static globals — no runtime alloc) ----------
__device__ float  g_xn[NN * DD];                    // normalized embeddings fp32 (8 MB)
__device__ __nv_bfloat16 g_Mt[384 * NN];            // Mᵀ bf16: rows 0-127 = Pᵀ, 128-383 = Xnᵀ (6 MB)
__device__ double g_acc[3];                         // 0: coherence, 1: structure SSE
__device__ double g_accW[32];                       // weight-loss per-block partials
__device__ unsigned int g_done;                     // finisher ticket (reset by finisher)

// ---------------------------------------------------------------------------
__device__ __forceinline__ uint32_t smem_u32(const void* p) {
    return (uint32_t)__cvta_generic_to_shared(p);
}

__device__ __forceinline__ float block_reduce_sum(float v) {
    __shared__ float red[8];
    int lane = threadIdx.x & 31;
    int wid  = threadIdx.x >> 5;
    #pragma unroll
    for (int o = 16; o > 0; o >>= 1) v += __shfl_xor_sync(0xffffffffu, v, o);
    if (lane == 0) red[wid] = v;
    __syncthreads();
    if (wid == 0) {
        v = (lane < ((int)blockDim.x >> 5)) ? red[lane] : 0.0f;
        #pragma unroll
        for (int o = 4; o > 0; o >>= 1) v += __shfl_xor_sync(0xffffffffu, v, o);
    }
    return v;
}

// ---------------------------------------------------------------------------
// PREP1: normalize -> g_xn | P transpose -> Mt rows 0-127 | weight partials | zero
#define PREP_NORM   8192
#define PREP_CONV   (PREP_NORM + 1024)
#define PREP_WEIGHT (PREP_CONV + 32)
#define PREP_TOTAL  (PREP_WEIGHT + 1)

__global__ void k_prep1(const float* __restrict__ X, const float* __restrict__ Pr,
                        const float* __restrict__ W) {
    int b = blockIdx.x;
    int t = threadIdx.x;

    if (b < PREP_NORM) {
        float x = X[(size_t)b * DD + t];
        float ss = block_reduce_sum(x * x);
        __shared__ float s_inv;
        if (t == 0) s_inv = 1.0f / fmaxf(sqrtf(ss), 1e-8f);
        __syncthreads();
        g_xn[(size_t)b * DD + t] = x * s_inv;
    } else if (b < PREP_CONV) {
        // P [8192,128] fp32 -> Mt rows 0-127 bf16 (transpose via 32x32 smem tile)
        int b2 = b - PREP_NORM;
        __shared__ float tt[32][33];
        int kb = (b2 >> 2) * 32;
        int nb = (b2 & 3) * 32;
        int tx = t & 31, ty = t >> 5;
        #pragma unroll
        for (int r = ty; r < 32; r += 8)
            tt[r][tx] = Pr[(size_t)(kb + r) * PP + nb + tx];
        __syncthreads();
        #pragma unroll
        for (int r = ty; r < 32; r += 8)
            g_Mt[(size_t)(nb + r) * NN + kb + tx] = __float2bfloat16(tt[tx][r]);
    } else if (b < PREP_WEIGHT) {
        int b2 = b - PREP_CONV;
        float s = 0.0f;
        int stride = 32 * 256;
        for (int i = b2 * 256 + t; i < NN * PP; i += stride) {
            float d = Pr[i] - W[i];
            s += d * d;
        }
        s = block_reduce_sum(s);
        if (t == 0) g_accW[b2] = (double)s;
    } else {
        if (t < 3) g_acc[t] = 0.0;
        if (t == 3) g_done = 0u;
    }
}

// PREP2: g_xn [8192,256] fp32 -> Mt rows 128-383 bf16 (transpose)
__global__ void k_prep2() {
    __shared__ float tt[32][33];
    int b = blockIdx.x;            // 2048 blocks: 256 k-tiles x 8 d-tiles
    int kb = (b >> 3) * 32;
    int db = (b & 7) * 32;
    int t = threadIdx.x;
    int tx = t & 31, ty = t >> 5;
    #pragma unroll
    for (int r = ty; r < 32; r += 8)
        tt[r][tx] = g_xn[(size_t)(kb + r) * DD + db + tx];
    __syncthreads();
    #pragma unroll
    for (int r = ty; r < 32; r += 8)
        g_Mt[(size_t)(128 + db + r) * NN + kb + tx] = __float2bfloat16(tt[tx][r]);
}

// ---------------------------------------------------------------------------
// MAIN: 128 structure CTAs (S = A@P, fused SSE) + 18 gram CTAs (G tiles, fused
// coherence). Identical tile shape / MAC count per CTA -> one uniform wave.
#define STRUCT_BLOCKS 128
#define GRAM_BLOCKS 18           // 6 r-blocks (64) x 3 c-blocks (128)
#define GRID_MAIN (STRUCT_BLOCKS + GRAM_BLOCKS)

#define KT 64
#define APAD 72

__device__ __forceinline__ void ldmx4(uint32_t& r0, uint32_t& r1, uint32_t& r2,
                                      uint32_t& r3, uint32_t addr) {
    asm volatile("ldmatrix.sync.aligned.m8n8.x4.shared.b16 {%0,%1,%2,%3}, [%4];"
                 : "=r"(r0), "=r"(r1), "=r"(r2), "=r"(r3) : "r"(addr));
}
__device__ __forceinline__ void mma_bf16(float* c, uint32_t a0, uint32_t a1,
                                         uint32_t a2, uint32_t a3,
                                         uint32_t b0, uint32_t b1) {
    asm volatile(
        "mma.sync.aligned.m16n8k16.row.col.f32.bf16.bf16.f32 "
        "{%0,%1,%2,%3}, {%4,%5,%6,%7}, {%8,%9}, {%0,%1,%2,%3};"
        : "+f"(c[0]), "+f"(c[1]), "+f"(c[2]), "+f"(c[3])
        : "r"(a0), "r"(a1), "r"(a2), "r"(a3), "r"(b0), "r"(b1));
}

// Shared GEMM body. GRAM=false: A = adj fp32 (convert in regs), B = Mt rows 0-127,
// epilogue = SSE vs P. GRAM=true: A = Mt r-block bf16, B = Mt c-block, epilogue =
// signed-square coherence partial.
template <bool GRAM>
__device__ __forceinline__ void gemm_body(const float* __restrict__ Af32,
                                          const __nv_bfloat16* __restrict__ Abf,
                                          const __nv_bfloat16* __restrict__ Bbf,
                                          const float* __restrict__ Pr,
                                          int r_base, int c_base,
                                          __nv_bfloat16* sA, __nv_bfloat16* sB) {
    int tid  = threadIdx.x;
    int wid  = tid >> 5;
    int lane = tid & 31;
    int gid  = lane >> 2;
    int tid4 = lane & 3;
    int wm   = wid >> 1;
    int wn   = wid & 1;

    int lrow = (lane & 7) + ((lane >> 3) & 1) * 8;
    int lk8  = (lane >> 4) * 8;

    uint32_t sA_u = smem_u32(sA);
    uint32_t sB_u = smem_u32(sB);

    float4 rA[4];      // structure: fp32 A staging
    uint4  rAg[2];     // gram: bf16 A staging
    uint4  rB[4];

    // preload iter 0
    #pragma unroll
    for (int q = 0; q < 4; q++) {
        int c = tid + q * 256;
        if (!GRAM)
            rA[q] = *(const float4*)&Af32[(size_t)(c >> 4) * NN + (c & 15) * 4];
        rB[q] = *(const uint4*)&Bbf[(size_t)(c >> 3) * NN + (c & 7) * 8];
    }
    if (GRAM) {
        #pragma unroll
        for (int q = 0; q < 2; q++) {
            int c = tid + q * 256;
            rAg[q] = *(const uint4*)&Abf[(size_t)(c >> 3) * NN + (c & 7) * 8];
        }
    }

    float acc[8][4] = {};

    const int NIT = NN / KT;
    for (int it = 0; it < NIT; it++) {
        // stage -> smem
        if (!GRAM) {
            #pragma unroll
            for (int q = 0; q < 4; q++) {
                int c = tid + q * 256;
                __nv_bfloat162 lo = __floats2bfloat162_rn(rA[q].x, rA[q].y);
                __nv_bfloat162 hi = __floats2bfloat162_rn(rA[q].z, rA[q].w);
                uint2 o; o.x = *(uint32_t*)&lo; o.y = *(uint32_t*)&hi;
                *(uint2*)&sA[(c >> 4) * APAD + (c & 15) * 4] = o;
            }
        } else {
            #pragma unroll
            for (int q = 0; q < 2; q++) {
                int c = tid + q * 256;
                *(uint4*)&sA[(c >> 3) * APAD + (c & 7) * 8] = rAg[q];
            }
        }
        #pragma unroll
        for (int q = 0; q < 4; q++) {
            int c = tid + q * 256;
            *(uint4*)&sB[(c >> 3) * APAD + (c & 7) * 8] = rB[q];
        }
        __syncthreads();

        // prefetch next tile
        if (it + 1 < NIT) {
            int k0 = (it + 1) * KT;
            #pragma unroll
            for (int q = 0; q < 4; q++) {
                int c = tid + q * 256;
                if (!GRAM)
                    rA[q] = *(const float4*)&Af32[(size_t)(c >> 4) * NN + k0 + (c & 15) * 4];
                rB[q] = *(const uint4*)&Bbf[(size_t)(c >> 3) * NN + k0 + (c & 7) * 8];
            }
            if (GRAM) {
                #pragma unroll
                for (int q = 0; q < 2; q++) {
                    int c = tid + q * 256;
                    rAg[q] = *(const uint4*)&Abf[(size_t)(c >> 3) * NN + k0 + (c & 7) * 8];
                }
            }
        }

        // compute KT=64 in four k16 steps
        #pragma unroll
        for (int kk = 0; kk < KT; kk += 16) {
            uint32_t a0, a1, a2, a3;
            ldmx4(a0, a1, a2, a3,
                  sA_u + ((wm * 16 + lrow) * APAD + kk + lk8) * 2);
            #pragma unroll
            for (int bt = 0; bt < 4; bt++) {
                uint32_t b0, b1, b2, b3;
                ldmx4(b0, b1, b2, b3,
                      sB_u + ((wn * 64 + bt * 16 + lrow) * APAD + kk + lk8) * 2);
                mma_bf16(acc[bt * 2 + 0], a0, a1, a2, a3, b0, b2);
                mma_bf16(acc[bt * 2 + 1], a0, a1, a2, a3, b1, b3);
            }
        }
        __syncthreads();
    }

    // epilogue
    float s = 0.0f;
    #pragma unroll
    for (int nt = 0; nt < 8; nt++) {
        int col = wn * 64 + nt * 8 + tid4 * 2;
        int m0 = wm * 16 + gid;
        if (!GRAM) {
            int m = r_base + m0;
            float p00 = Pr[(size_t)m * PP + col];
            float p01 = Pr[(size_t)m * PP + col + 1];
            float p10 = Pr[(size_t)(m + 8) * PP + col];
            float p11 = Pr[(size_t)(m + 8) * PP + col + 1];
            float d0 = p00 - acc[nt][0];
            float d1 = p01 - acc[nt][1];
            float d2 = p10 - acc[nt][2];
            float d3 = p11 - acc[nt][3];
            s += d0 * d0 + d1 * d1 + d2 * d2 + d3 * d3;
        } else {
            // coherence partial: sum sgn(r,c) * G^2
            int r0g = r_base + m0;
            int r1g = r0g + 8;
            int c0g = c_base + col;
            int c1g = c0g + 1;
            float s00 = ((r0g < 128) == (c0g < 128)) ? 1.0f : -1.0f;
            float s01 = ((r0g < 128) == (c1g < 128)) ? 1.0f : -1.0f;
            float s10 = ((r1g < 128) == (c0g < 128)) ? 1.0f : -1.0f;
            float s11 = ((r1g < 128) == (c1g < 128)) ? 1.0f : -1.0f;
            s += s00 * acc[nt][0] * acc[nt][0] + s01 * acc[nt][1] * acc[nt][1]
               + s10 * acc[nt][2] * acc[nt][2] + s11 * acc[nt][3] * acc[nt][3];
        }
    }
    s = block_reduce_sum(s);
    if (tid == 0) atomicAdd(&g_acc[GRAM ? 0 : 1], (double)s);
}

__global__ void __launch_bounds__(256) k_main(const float* __restrict__ A,
                                              const float* __restrict__ Pr,
                                              float* __restrict__ out) {
    __shared__ __align__(16) __nv_bfloat16 sA[64 * APAD];
    __shared__ __align__(16) __nv_bfloat16 sB[128 * APAD];

    int bid = blockIdx.x;
    if (bid < STRUCT_BLOCKS) {
        gemm_body<false>(A + (size_t)bid * 64 * NN, nullptr, g_Mt, Pr,
                         bid * 64, 0, sA, sB);
    } else {
        int g = bid - STRUCT_BLOCKS;          // 0..17
        int rblk = g / 3, cblk = g % 3;
        gemm_body<true>(nullptr,
                        g_Mt + (size_t)(rblk * 64) * NN,
                        g_Mt + (size_t)(cblk * 128) * NN,
                        Pr, rblk * 64, cblk * 128, sA, sB);
    }

    // last-block finisher
    __shared__ unsigned int s_ticket;
    __threadfence();
    if (threadIdx.x == 0) s_ticket = atomicAdd(&g_done, 1u);
    __syncthreads();
    if (s_ticket == GRID_MAIN - 1) {
        if (threadIdx.x == 0) {
            double w = 0.0;
            #pragma unroll
            for (int i = 0; i < 32; i++) w += g_accW[i];
            double nn = (double)NN * (double)NN;
            double np = (double)NN * (double)PP;
            out[0] = (float)(g_acc[0] / nn + g_acc[1] / np + w / np);
            g_done = 0u;   // reset for next graph replay
        }
    }
}

// ---------------------------------------------------------------------------
extern "C" void kernel_launch(void* const* d_in, const int* in_sizes, int n_in,
                              void* d_out, int out_size) {
    const float* preds = (const float*)d_in[0];   // [8192, 128]
    const float* emb   = (const float*)d_in[1];   // [8192, 256]
    const float* adj   = (const float*)d_in[2];   // [8192, 8192]
    const float* wts   = (const float*)d_in[3];   // [8192, 128]
    float* out = (float*)d_out;

    k_prep1<<<PREP_TOTAL, 256>>>(emb, preds, wts);
    k_prep2<<<2048, 256>>>();
    k_main<<<GRID_MAIN, 256>>>(adj, preds, out);
}

// round 8
// speedup vs baseline: 6.9670x; 1.0600x over previous
#include <cuda_runtime.h>
#include <cuda_bf16.h>
#include <math.h>
#include <stdint.h>

#define NN 8192
#define PP 128
#define DD 256

// ---------------- device scratch (static globals — no runtime alloc) ----------
__device__ float  g_inorm[NN];                      // 1/max(||x||,eps) per row
__device__ __nv_bfloat16 g_Mt[384 * NN];            // Mᵀ bf16: rows 0-127 = Pᵀ, 128-383 = Xnᵀ (6 MB)
__device__ double g_acc[3];                         // 0: coherence, 1: structure SSE
__device__ double g_accW[32];                       // weight-loss per-block partials
__device__ unsigned int g_done;                     // finisher ticket (reset by finisher)

// ---------------------------------------------------------------------------
__device__ __forceinline__ uint32_t smem_u32(const void* p) {
    return (uint32_t)__cvta_generic_to_shared(p);
}

__device__ __forceinline__ float block_reduce_sum(float v) {
    __shared__ float red[8];
    int lane = threadIdx.x & 31;
    int wid  = threadIdx.x >> 5;
    #pragma unroll
    for (int o = 16; o > 0; o >>= 1) v += __shfl_xor_sync(0xffffffffu, v, o);
    if (lane == 0) red[wid] = v;
    __syncthreads();
    if (wid == 0) {
        v = (lane < ((int)blockDim.x >> 5)) ? red[lane] : 0.0f;
        #pragma unroll
        for (int o = 4; o > 0; o >>= 1) v += __shfl_xor_sync(0xffffffffu, v, o);
    }
    return v;
}

// ---------------------------------------------------------------------------
// K_NORMS: warp-per-row inv-norms | weight partials | zero accumulators
#define NORM_BLOCKS   1024
#define WEIGHT_BLOCKS 32
#define NORMS_GRID    (NORM_BLOCKS + WEIGHT_BLOCKS + 1)

__global__ void k_norms(const float* __restrict__ X, const float* __restrict__ Pr,
                        const float* __restrict__ W) {
    int b = blockIdx.x;
    int t = threadIdx.x;
    int lane = t & 31;
    int wid  = t >> 5;

    if (b < NORM_BLOCKS) {
        int row = b * 8 + wid;
        const float4* xr = (const float4*)&X[(size_t)row * DD];
        float4 v0 = xr[lane * 2];
        float4 v1 = xr[lane * 2 + 1];
        float ss = v0.x * v0.x + v0.y * v0.y + v0.z * v0.z + v0.w * v0.w
                 + v1.x * v1.x + v1.y * v1.y + v1.z * v1.z + v1.w * v1.w;
        #pragma unroll
        for (int o = 16; o > 0; o >>= 1) ss += __shfl_xor_sync(0xffffffffu, ss, o);
        if (lane == 0) g_inorm[row] = 1.0f / fmaxf(sqrtf(ss), 1e-8f);
    } else if (b < NORM_BLOCKS + WEIGHT_BLOCKS) {
        int b2 = b - NORM_BLOCKS;
        float s = 0.0f;
        const float4* P4 = (const float4*)Pr;
        const float4* W4 = (const float4*)W;
        for (int i = b2 * 256 + t; i < NN * PP / 4; i += WEIGHT_BLOCKS * 256) {
            float4 p = P4[i], w = W4[i];
            float d0 = p.x - w.x, d1 = p.y - w.y, d2 = p.z - w.z, d3 = p.w - w.w;
            s += d0 * d0 + d1 * d1 + d2 * d2 + d3 * d3;
        }
        s = block_reduce_sum(s);
        if (t == 0) g_accW[b2] = (double)s;
    } else {
        if (t < 3) g_acc[t] = 0.0;
        if (t == 3) g_done = 0u;
    }
}

// ---------------------------------------------------------------------------
// K_PREP_T: 64x64-tile transposes into Mt. Gmem loads are float4; smem stores
// are SCALAR (tt rows are 65 floats -> float4 would be misaligned).
#define XT_BLOCKS 512
#define PT_BLOCKS 256
#define PREPT_GRID (XT_BLOCKS + PT_BLOCKS)

__global__ void k_prep_t(const float* __restrict__ X, const float* __restrict__ Pr) {
    __shared__ float tt[64][65];
    __shared__ float sI[64];

    int b = blockIdx.x;
    int t = threadIdx.x;
    int tx = t & 15, ty = t >> 4;    // tx: 4-col group, ty: row 0..15

    if (b < XT_BLOCKS) {
        int kb = (b >> 2) * 64;      // n-base (source row)
        int db = (b & 3) * 64;       // d-base (source col)
        #pragma unroll
        for (int r = ty; r < 64; r += 16) {
            float4 v = *(const float4*)&X[(size_t)(kb + r) * DD + db + tx * 4];
            tt[r][tx * 4 + 0] = v.x;
            tt[r][tx * 4 + 1] = v.y;
            tt[r][tx * 4 + 2] = v.z;
            tt[r][tx * 4 + 3] = v.w;
        }
        if (t < 64) sI[t] = g_inorm[kb + t];
        __syncthreads();
        #pragma unroll
        for (int rr = ty; rr < 64; rr += 16) {
            int cc = tx * 4;
            float f0 = tt[cc + 0][rr] * sI[cc + 0];
            float f1 = tt[cc + 1][rr] * sI[cc + 1];
            float f2 = tt[cc + 2][rr] * sI[cc + 2];
            float f3 = tt[cc + 3][rr] * sI[cc + 3];
            __nv_bfloat162 lo = __floats2bfloat162_rn(f0, f1);
            __nv_bfloat162 hi = __floats2bfloat162_rn(f2, f3);
            uint2 o; o.x = *(uint32_t*)&lo; o.y = *(uint32_t*)&hi;
            *(uint2*)&g_Mt[(size_t)(128 + db + rr) * NN + kb + cc] = o;
        }
    } else {
        int b2 = b - XT_BLOCKS;
        int kb = (b2 >> 1) * 64;     // n-base
        int pb = (b2 & 1) * 64;      // p-base
        #pragma unroll
        for (int r = ty; r < 64; r += 16) {
            float4 v = *(const float4*)&Pr[(size_t)(kb + r) * PP + pb + tx * 4];
            tt[r][tx * 4 + 0] = v.x;
            tt[r][tx * 4 + 1] = v.y;
            tt[r][tx * 4 + 2] = v.z;
            tt[r][tx * 4 + 3] = v.w;
        }
        __syncthreads();
        #pragma unroll
        for (int rr = ty; rr < 64; rr += 16) {
            int cc = tx * 4;
            __nv_bfloat162 lo = __floats2bfloat162_rn(tt[cc + 0][rr], tt[cc + 1][rr]);
            __nv_bfloat162 hi = __floats2bfloat162_rn(tt[cc + 2][rr], tt[cc + 3][rr]);
            uint2 o; o.x = *(uint32_t*)&lo; o.y = *(uint32_t*)&hi;
            *(uint2*)&g_Mt[(size_t)(pb + rr) * NN + kb + cc] = o;
        }
    }
}

// ---------------------------------------------------------------------------
// MAIN: 128 structure CTAs (S = A@P, fused SSE) + 18 gram CTAs (G tiles, fused
// coherence). Identical tile shape / MAC count per CTA -> one uniform wave.
#define STRUCT_BLOCKS 128
#define GRAM_BLOCKS 18
#define GRID_MAIN (STRUCT_BLOCKS + GRAM_BLOCKS)

#define KT 64
#define APAD 72

__device__ __forceinline__ void ldmx4(uint32_t& r0, uint32_t& r1, uint32_t& r2,
                                      uint32_t& r3, uint32_t addr) {
    asm volatile("ldmatrix.sync.aligned.m8n8.x4.shared.b16 {%0,%1,%2,%3}, [%4];"
                 : "=r"(r0), "=r"(r1), "=r"(r2), "=r"(r3) : "r"(addr));
}
__device__ __forceinline__ void mma_bf16(float* c, uint32_t a0, uint32_t a1,
                                         uint32_t a2, uint32_t a3,
                                         uint32_t b0, uint32_t b1) {
    asm volatile(
        "mma.sync.aligned.m16n8k16.row.col.f32.bf16.bf16.f32 "
        "{%0,%1,%2,%3}, {%4,%5,%6,%7}, {%8,%9}, {%0,%1,%2,%3};"
        : "+f"(c[0]), "+f"(c[1]), "+f"(c[2]), "+f"(c[3])
        : "r"(a0), "r"(a1), "r"(a2), "r"(a3), "r"(b0), "r"(b1));
}

template <bool GRAM>
__device__ __forceinline__ void gemm_body(const float* __restrict__ Af32,
                                          const __nv_bfloat16* __restrict__ Abf,
                                          const __nv_bfloat16* __restrict__ Bbf,
                                          const float* __restrict__ Pr,
                                          int r_base, int c_base,
                                          __nv_bfloat16* sA, __nv_bfloat16* sB) {
    int tid  = threadIdx.x;
    int wid  = tid >> 5;
    int lane = tid & 31;
    int gid  = lane >> 2;
    int tid4 = lane & 3;
    int wm   = wid >> 1;
    int wn   = wid & 1;

    int lrow = (lane & 7) + ((lane >> 3) & 1) * 8;
    int lk8  = (lane >> 4) * 8;

    uint32_t sA_u = smem_u32(sA);
    uint32_t sB_u = smem_u32(sB);

    float4 rA[4];
    uint4  rAg[2];
    uint4  rB[4];

    #pragma unroll
    for (int q = 0; q < 4; q++) {
        int c = tid + q * 256;
        if (!GRAM)
            rA[q] = *(const float4*)&Af32[(size_t)(c >> 4) * NN + (c & 15) * 4];
        rB[q] = *(const uint4*)&Bbf[(size_t)(c >> 3) * NN + (c & 7) * 8];
    }
    if (GRAM) {
        #pragma unroll
        for (int q = 0; q < 2; q++) {
            int c = tid + q * 256;
            rAg[q] = *(const uint4*)&Abf[(size_t)(c >> 3) * NN + (c & 7) * 8];
        }
    }

    float acc[8][4] = {};

    const int NIT = NN / KT;
    for (int it = 0; it < NIT; it++) {
        if (!GRAM) {
            #pragma unroll
            for (int q = 0; q < 4; q++) {
                int c = tid + q * 256;
                __nv_bfloat162 lo = __floats2bfloat162_rn(rA[q].x, rA[q].y);
                __nv_bfloat162 hi = __floats2bfloat162_rn(rA[q].z, rA[q].w);
                uint2 o; o.x = *(uint32_t*)&lo; o.y = *(uint32_t*)&hi;
                *(uint2*)&sA[(c >> 4) * APAD + (c & 15) * 4] = o;
            }
        } else {
            #pragma unroll
            for (int q = 0; q < 2; q++) {
                int c = tid + q * 256;
                *(uint4*)&sA[(c >> 3) * APAD + (c & 7) * 8] = rAg[q];
            }
        }
        #pragma unroll
        for (int q = 0; q < 4; q++) {
            int c = tid + q * 256;
            *(uint4*)&sB[(c >> 3) * APAD + (c & 7) * 8] = rB[q];
        }
        __syncthreads();

        if (it + 1 < NIT) {
            int k0 = (it + 1) * KT;
            #pragma unroll
            for (int q = 0; q < 4; q++) {
                int c = tid + q * 256;
                if (!GRAM)
                    rA[q] = *(const float4*)&Af32[(size_t)(c >> 4) * NN + k0 + (c & 15) * 4];
                rB[q] = *(const uint4*)&Bbf[(size_t)(c >> 3) * NN + k0 + (c & 7) * 8];
            }
            if (GRAM) {
                #pragma unroll
                for (int q = 0; q < 2; q++) {
                    int c = tid + q * 256;
                    rAg[q] = *(const uint4*)&Abf[(size_t)(c >> 3) * NN + k0 + (c & 7) * 8];
                }
            }
        }

        #pragma unroll
        for (int kk = 0; kk < KT; kk += 16) {
            uint32_t a0, a1, a2, a3;
            ldmx4(a0, a1, a2, a3,
                  sA_u + ((wm * 16 + lrow) * APAD + kk + lk8) * 2);
            #pragma unroll
            for (int bt = 0; bt < 4; bt++) {
                uint32_t b0, b1, b2, b3;
                ldmx4(b0, b1, b2, b3,
                      sB_u + ((wn * 64 + bt * 16 + lrow) * APAD + kk + lk8) * 2);
                mma_bf16(acc[bt * 2 + 0], a0, a1, a2, a3, b0, b2);
                mma_bf16(acc[bt * 2 + 1], a0, a1, a2, a3, b1, b3);
            }
        }
        __syncthreads();
    }

    float s = 0.0f;
    #pragma unroll
    for (int nt = 0; nt < 8; nt++) {
        int col = wn * 64 + nt * 8 + tid4 * 2;
        int m0 = wm * 16 + gid;
        if (!GRAM) {
            int m = r_base + m0;
            float p00 = Pr[(size_t)m * PP + col];
            float p01 = Pr[(size_t)m * PP + col + 1];
            float p10 = Pr[(size_t)(m + 8) * PP + col];
            float p11 = Pr[(size_t)(m + 8) * PP + col + 1];
            float d0 = p00 - acc[nt][0];
            float d1 = p01 - acc[nt][1];
            float d2 = p10 - acc[nt][2];
            float d3 = p11 - acc[nt][3];
            s += d0 * d0 + d1 * d1 + d2 * d2 + d3 * d3;
        } else {
            int r0g = r_base + m0;
            int r1g = r0g + 8;
            int c0g = c_base + col;
            int c1g = c0g + 1;
            float s00 = ((r0g < 128) == (c0g < 128)) ? 1.0f : -1.0f;
            float s01 = ((r0g < 128) == (c1g < 128)) ? 1.0f : -1.0f;
            float s10 = ((r1g < 128) == (c0g < 128)) ? 1.0f : -1.0f;
            float s11 = ((r1g < 128) == (c1g < 128)) ? 1.0f : -1.0f;
            s += s00 * acc[nt][0] * acc[nt][0] + s01 * acc[nt][1] * acc[nt][1]
               + s10 * acc[nt][2] * acc[nt][2] + s11 * acc[nt][3] * acc[nt][3];
        }
    }
    s = block_reduce_sum(s);
    if (tid == 0) atomicAdd(&g_acc[GRAM ? 0 : 1], (double)s);
}

__global__ void __launch_bounds__(256) k_main(const float* __restrict__ A,
                                              const float* __restrict__ Pr,
                                              float* __restrict__ out) {
    __shared__ __align__(16) __nv_bfloat16 sA[64 * APAD];
    __shared__ __align__(16) __nv_bfloat16 sB[128 * APAD];

    int bid = blockIdx.x;
    if (bid < STRUCT_BLOCKS) {
        gemm_body<false>(A + (size_t)bid * 64 * NN, nullptr, g_Mt, Pr,
                         bid * 64, 0, sA, sB);
    } else {
        int g = bid - STRUCT_BLOCKS;
        int rblk = g / 3, cblk = g % 3;
        gemm_body<true>(nullptr,
                        g_Mt + (size_t)(rblk * 64) * NN,
                        g_Mt + (size_t)(cblk * 128) * NN,
                        Pr, rblk * 64, cblk * 128, sA, sB);
    }

    __shared__ unsigned int s_ticket;
    __threadfence();
    if (threadIdx.x == 0) s_ticket = atomicAdd(&g_done, 1u);
    __syncthreads();
    if (s_ticket == GRID_MAIN - 1) {
        if (threadIdx.x == 0) {
            double w = 0.0;
            #pragma unroll
            for (int i = 0; i < 32; i++) w += g_accW[i];
            double nn = (double)NN * (double)NN;
            double np = (double)NN * (double)PP;
            out[0] = (float)(g_acc[0] / nn + g_acc[1] / np + w / np);
            g_done = 0u;
        }
    }
}

// ---------------------------------------------------------------------------
extern "C" void kernel_launch(void* const* d_in, const int* in_sizes, int n_in,
                              void* d_out, int out_size) {
    const float* preds = (const float*)d_in[0];   // [8192, 128]
    const float* emb   = (const float*)d_in[1];   // [8192, 256]
    const float* adj   = (const float*)d_in[2];   // [8192, 8192]
    const float* wts   = (const float*)d_in[3];   // [8192, 128]
    float* out = (float*)d_out;

    k_norms<<<NORMS_GRID, 256>>>(emb, preds, wts);
    k_prep_t<<<PREPT_GRID, 256>>>(emb, preds);
    k_main<<<GRID_MAIN, 256>>>(adj, preds, out);
}

// round 9
// speedup vs baseline: 7.8398x; 1.1253x over previous
#include <cuda_runtime.h>
#include <cuda_bf16.h>
#include <math.h>
#include <stdint.h>

#define NN 8192
#define PP 128
#define DD 256

// ---------------- device scratch (static globals — no runtime alloc) ----------
__device__ float  g_inorm[NN];                      // 1/max(||x||,eps) per row
__device__ __nv_bfloat16 g_Mt[384 * NN];            // Mᵀ bf16: rows 0-127 = Pᵀ, 128-383 = Xnᵀ (6 MB)
__device__ double g_acc[2];                         // 0: coherence, 1: structure+weight SSE
__device__ unsigned int g_done;                     // finisher ticket (reset by finisher)

// ---------------------------------------------------------------------------
__device__ __forceinline__ uint32_t smem_u32(const void* p) {
    return (uint32_t)__cvta_generic_to_shared(p);
}

__device__ __forceinline__ float block_reduce_sum(float v) {
    __shared__ float red[8];
    int lane = threadIdx.x & 31;
    int wid  = threadIdx.x >> 5;
    #pragma unroll
    for (int o = 16; o > 0; o >>= 1) v += __shfl_xor_sync(0xffffffffu, v, o);
    if (lane == 0) red[wid] = v;
    __syncthreads();
    if (wid == 0) {
        v = (lane < ((int)blockDim.x >> 5)) ? red[lane] : 0.0f;
        #pragma unroll
        for (int o = 4; o > 0; o >>= 1) v += __shfl_xor_sync(0xffffffffu, v, o);
    }
    return v;
}

// ---------------------------------------------------------------------------
// K_NORMS: warp-per-row inv-norms (8 rows per 256-thread block) + zero block
#define NORM_BLOCKS 1024
#define NORMS_GRID  (NORM_BLOCKS + 1)

__global__ void k_norms(const float* __restrict__ X) {
    int b = blockIdx.x;
    int t = threadIdx.x;
    int lane = t & 31;
    int wid  = t >> 5;

    if (b < NORM_BLOCKS) {
        int row = b * 8 + wid;
        const float4* xr = (const float4*)&X[(size_t)row * DD];
        float4 v0 = xr[lane * 2];
        float4 v1 = xr[lane * 2 + 1];
        float ss = v0.x * v0.x + v0.y * v0.y + v0.z * v0.z + v0.w * v0.w
                 + v1.x * v1.x + v1.y * v1.y + v1.z * v1.z + v1.w * v1.w;
        #pragma unroll
        for (int o = 16; o > 0; o >>= 1) ss += __shfl_xor_sync(0xffffffffu, ss, o);
        if (lane == 0) g_inorm[row] = 1.0f / fmaxf(sqrtf(ss), 1e-8f);
    } else {
        if (t < 2) g_acc[t] = 0.0;
        if (t == 2) g_done = 0u;
    }
}

// ---------------------------------------------------------------------------
// K_PREP_T: 64x64-tile transposes into Mt. Gmem loads are float4; smem stores
// are SCALAR (tt rows are 65 floats -> float4 would be misaligned).
#define XT_BLOCKS 512
#define PT_BLOCKS 256
#define PREPT_GRID (XT_BLOCKS + PT_BLOCKS)

__global__ void k_prep_t(const float* __restrict__ X, const float* __restrict__ Pr) {
    __shared__ float tt[64][65];
    __shared__ float sI[64];

    int b = blockIdx.x;
    int t = threadIdx.x;
    int tx = t & 15, ty = t >> 4;    // tx: 4-col group, ty: row 0..15

    if (b < XT_BLOCKS) {
        int kb = (b >> 2) * 64;      // n-base (source row)
        int db = (b & 3) * 64;       // d-base (source col)
        #pragma unroll
        for (int r = ty; r < 64; r += 16) {
            float4 v = *(const float4*)&X[(size_t)(kb + r) * DD + db + tx * 4];
            tt[r][tx * 4 + 0] = v.x;
            tt[r][tx * 4 + 1] = v.y;
            tt[r][tx * 4 + 2] = v.z;
            tt[r][tx * 4 + 3] = v.w;
        }
        if (t < 64) sI[t] = g_inorm[kb + t];
        __syncthreads();
        #pragma unroll
        for (int rr = ty; rr < 64; rr += 16) {
            int cc = tx * 4;
            float f0 = tt[cc + 0][rr] * sI[cc + 0];
            float f1 = tt[cc + 1][rr] * sI[cc + 1];
            float f2 = tt[cc + 2][rr] * sI[cc + 2];
            float f3 = tt[cc + 3][rr] * sI[cc + 3];
            __nv_bfloat162 lo = __floats2bfloat162_rn(f0, f1);
            __nv_bfloat162 hi = __floats2bfloat162_rn(f2, f3);
            uint2 o; o.x = *(uint32_t*)&lo; o.y = *(uint32_t*)&hi;
            *(uint2*)&g_Mt[(size_t)(128 + db + rr) * NN + kb + cc] = o;
        }
    } else {
        int b2 = b - XT_BLOCKS;
        int kb = (b2 >> 1) * 64;     // n-base
        int pb = (b2 & 1) * 64;      // p-base
        #pragma unroll
        for (int r = ty; r < 64; r += 16) {
            float4 v = *(const float4*)&Pr[(size_t)(kb + r) * PP + pb + tx * 4];
            tt[r][tx * 4 + 0] = v.x;
            tt[r][tx * 4 + 1] = v.y;
            tt[r][tx * 4 + 2] = v.z;
            tt[r][tx * 4 + 3] = v.w;
        }
        __syncthreads();
        #pragma unroll
        for (int rr = ty; rr < 64; rr += 16) {
            int cc = tx * 4;
            __nv_bfloat162 lo = __floats2bfloat162_rn(tt[cc + 0][rr], tt[cc + 1][rr]);
            __nv_bfloat162 hi = __floats2bfloat162_rn(tt[cc + 2][rr], tt[cc + 3][rr]);
            uint2 o; o.x = *(uint32_t*)&lo; o.y = *(uint32_t*)&hi;
            *(uint2*)&g_Mt[(size_t)(pb + rr) * NN + kb + cc] = o;
        }
    }
}

// ---------------------------------------------------------------------------
// MAIN: 128 structure CTAs (S = A@P, fused SSE + weight SSE) + 18 gram CTAs
// (G tiles, fused coherence). One uniform wave.
#define STRUCT_BLOCKS 128
#define GRAM_BLOCKS 18
#define GRID_MAIN (STRUCT_BLOCKS + GRAM_BLOCKS)

#define KT 64
#define APAD 72

__device__ __forceinline__ void ldmx4(uint32_t& r0, uint32_t& r1, uint32_t& r2,
                                      uint32_t& r3, uint32_t addr) {
    asm volatile("ldmatrix.sync.aligned.m8n8.x4.shared.b16 {%0,%1,%2,%3}, [%4];"
                 : "=r"(r0), "=r"(r1), "=r"(r2), "=r"(r3) : "r"(addr));
}
__device__ __forceinline__ void mma_bf16(float* c, uint32_t a0, uint32_t a1,
                                         uint32_t a2, uint32_t a3,
                                         uint32_t b0, uint32_t b1) {
    asm volatile(
        "mma.sync.aligned.m16n8k16.row.col.f32.bf16.bf16.f32 "
        "{%0,%1,%2,%3}, {%4,%5,%6,%7}, {%8,%9}, {%0,%1,%2,%3};"
        : "+f"(c[0]), "+f"(c[1]), "+f"(c[2]), "+f"(c[3])
        : "r"(a0), "r"(a1), "r"(a2), "r"(a3), "r"(b0), "r"(b1));
}

template <bool GRAM>
__device__ __forceinline__ void gemm_body(const float* __restrict__ Af32,
                                          const __nv_bfloat16* __restrict__ Abf,
                                          const __nv_bfloat16* __restrict__ Bbf,
                                          const float* __restrict__ Pr,
                                          const float* __restrict__ W,
                                          int r_base, int c_base,
                                          __nv_bfloat16* sA, __nv_bfloat16* sB) {
    int tid  = threadIdx.x;
    int wid  = tid >> 5;
    int lane = tid & 31;
    int gid  = lane >> 2;
    int tid4 = lane & 3;
    int wm   = wid >> 1;
    int wn   = wid & 1;

    int lrow = (lane & 7) + ((lane >> 3) & 1) * 8;
    int lk8  = (lane >> 4) * 8;

    uint32_t sA_u = smem_u32(sA);
    uint32_t sB_u = smem_u32(sB);

    float4 rA[4];
    uint4  rAg[2];
    uint4  rB[4];

    #pragma unroll
    for (int q = 0; q < 4; q++) {
        int c = tid + q * 256;
        if (!GRAM)
            rA[q] = *(const float4*)&Af32[(size_t)(c >> 4) * NN + (c & 15) * 4];
        rB[q] = *(const uint4*)&Bbf[(size_t)(c >> 3) * NN + (c & 7) * 8];
    }
    if (GRAM) {
        #pragma unroll
        for (int q = 0; q < 2; q++) {
            int c = tid + q * 256;
            rAg[q] = *(const uint4*)&Abf[(size_t)(c >> 3) * NN + (c & 7) * 8];
        }
    }

    float acc[8][4] = {};

    const int NIT = NN / KT;
    for (int it = 0; it < NIT; it++) {
        if (!GRAM) {
            #pragma unroll
            for (int q = 0; q < 4; q++) {
                int c = tid + q * 256;
                __nv_bfloat162 lo = __floats2bfloat162_rn(rA[q].x, rA[q].y);
                __nv_bfloat162 hi = __floats2bfloat162_rn(rA[q].z, rA[q].w);
                uint2 o; o.x = *(uint32_t*)&lo; o.y = *(uint32_t*)&hi;
                *(uint2*)&sA[(c >> 4) * APAD + (c & 15) * 4] = o;
            }
        } else {
            #pragma unroll
            for (int q = 0; q < 2; q++) {
                int c = tid + q * 256;
                *(uint4*)&sA[(c >> 3) * APAD + (c & 7) * 8] = rAg[q];
            }
        }
        #pragma unroll
        for (int q = 0; q < 4; q++) {
            int c = tid + q * 256;
            *(uint4*)&sB[(c >> 3) * APAD + (c & 7) * 8] = rB[q];
        }
        __syncthreads();

        if (it + 1 < NIT) {
            int k0 = (it + 1) * KT;
            #pragma unroll
            for (int q = 0; q < 4; q++) {
                int c = tid + q * 256;
                if (!GRAM)
                    rA[q] = *(const float4*)&Af32[(size_t)(c >> 4) * NN + k0 + (c & 15) * 4];
                rB[q] = *(const uint4*)&Bbf[(size_t)(c >> 3) * NN + k0 + (c & 7) * 8];
            }
            if (GRAM) {
                #pragma unroll
                for (int q = 0; q < 2; q++) {
                    int c = tid + q * 256;
                    rAg[q] = *(const uint4*)&Abf[(size_t)(c >> 3) * NN + k0 + (c & 7) * 8];
                }
            }
        }

        #pragma unroll
        for (int kk = 0; kk < KT; kk += 16) {
            uint32_t a0, a1, a2, a3;
            ldmx4(a0, a1, a2, a3,
                  sA_u + ((wm * 16 + lrow) * APAD + kk + lk8) * 2);
            #pragma unroll
            for (int bt = 0; bt < 4; bt++) {
                uint32_t b0, b1, b2, b3;
                ldmx4(b0, b1, b2, b3,
                      sB_u + ((wn * 64 + bt * 16 + lrow) * APAD + kk + lk8) * 2);
                mma_bf16(acc[bt * 2 + 0], a0, a1, a2, a3, b0, b2);
                mma_bf16(acc[bt * 2 + 1], a0, a1, a2, a3, b1, b3);
            }
        }
        __syncthreads();
    }

    float s = 0.0f;
    #pragma unroll
    for (int nt = 0; nt < 8; nt++) {
        int col = wn * 64 + nt * 8 + tid4 * 2;
        int m0 = wm * 16 + gid;
        if (!GRAM) {
            int m = r_base + m0;
            float p00 = Pr[(size_t)m * PP + col];
            float p01 = Pr[(size_t)m * PP + col + 1];
            float p10 = Pr[(size_t)(m + 8) * PP + col];
            float p11 = Pr[(size_t)(m + 8) * PP + col + 1];
            // structure SSE
            float d0 = p00 - acc[nt][0];
            float d1 = p01 - acc[nt][1];
            float d2 = p10 - acc[nt][2];
            float d3 = p11 - acc[nt][3];
            s += d0 * d0 + d1 * d1 + d2 * d2 + d3 * d3;
            // weight SSE (same normalizer 1/(N*P) -> same accumulator)
            float w00 = W[(size_t)m * PP + col];
            float w01 = W[(size_t)m * PP + col + 1];
            float w10 = W[(size_t)(m + 8) * PP + col];
            float w11 = W[(size_t)(m + 8) * PP + col + 1];
            float e0 = p00 - w00, e1 = p01 - w01, e2 = p10 - w10, e3 = p11 - w11;
            s += e0 * e0 + e1 * e1 + e2 * e2 + e3 * e3;
        } else {
            int r0g = r_base + m0;
            int r1g = r0g + 8;
            int c0g = c_base + col;
            int c1g = c0g + 1;
            float s00 = ((r0g < 128) == (c0g < 128)) ? 1.0f : -1.0f;
            float s01 = ((r0g < 128) == (c1g < 128)) ? 1.0f : -1.0f;
            float s10 = ((r1g < 128) == (c0g < 128)) ? 1.0f : -1.0f;
            float s11 = ((r1g < 128) == (c1g < 128)) ? 1.0f : -1.0f;
            s += s00 * acc[nt][0] * acc[nt][0] + s01 * acc[nt][1] * acc[nt][1]
               + s10 * acc[nt][2] * acc[nt][2] + s11 * acc[nt][3] * acc[nt][3];
        }
    }
    s = block_reduce_sum(s);
    if (tid == 0) atomicAdd(&g_acc[GRAM ? 0 : 1], (double)s);
}

__global__ void __launch_bounds__(256) k_main(const float* __restrict__ A,
                                              const float* __restrict__ Pr,
                                              const float* __restrict__ W,
                                              float* __restrict__ out) {
    __shared__ __align__(16) __nv_bfloat16 sA[64 * APAD];
    __shared__ __align__(16) __nv_bfloat16 sB[128 * APAD];

    int bid = blockIdx.x;
    if (bid < STRUCT_BLOCKS) {
        gemm_body<false>(A + (size_t)bid * 64 * NN, nullptr, g_Mt, Pr, W,
                         bid * 64, 0, sA, sB);
    } else {
        int g = bid - STRUCT_BLOCKS;
        int rblk = g / 3, cblk = g % 3;
        gemm_body<true>(nullptr,
                        g_Mt + (size_t)(rblk * 64) * NN,
                        g_Mt + (size_t)(cblk * 128) * NN,
                        Pr, nullptr, rblk * 64, cblk * 128, sA, sB);
    }

    __shared__ unsigned int s_ticket;
    __threadfence();
    if (threadIdx.x == 0) s_ticket = atomicAdd(&g_done, 1u);
    __syncthreads();
    if (s_ticket == GRID_MAIN - 1) {
        if (threadIdx.x == 0) {
            double nn = (double)NN * (double)NN;
            double np = (double)NN * (double)PP;
            out[0] = (float)(g_acc[0] / nn + g_acc[1] / np);
            g_done = 0u;
        }
    }
}

// ---------------------------------------------------------------------------
extern "C" void kernel_launch(void* const* d_in, const int* in_sizes, int n_in,
                              void* d_out, int out_size) {
    const float* preds = (const float*)d_in[0];   // [8192, 128]
    const float* emb   = (const float*)d_in[1];   // [8192, 256]
    const float* adj   = (const float*)d_in[2];   // [8192, 8192]
    const float* wts   = (const float*)d_in[3];   // [8192, 128]
    float* out = (float*)d_out;

    k_norms<<<NORMS_GRID, 256>>>(emb);
    k_prep_t<<<PREPT_GRID, 256>>>(emb, preds);
    k_main<<<GRID_MAIN, 256>>>(adj, preds, wts, out);
}

// round 10
// speedup vs baseline: 8.4009x; 1.0716x over previous
#include <cuda_runtime.h>
#include <cuda_bf16.h>
#include <math.h>
#include <stdint.h>

#define NN 8192
#define PP 128
#define DD 256

// ---------------- device scratch (static globals — no runtime alloc) ----------
__device__ float  g_inorm[NN];                      // 1/max(||x||,eps) per row
__device__ __nv_bfloat16 g_Mt[384 * NN];            // Mᵀ bf16: rows 0-127 = Pᵀ, 128-383 = Xnᵀ
__device__ double g_acc[2];                         // 0: coherence, 1: structure+weight SSE
__device__ unsigned int g_done;                     // finisher ticket

// ---------------------------------------------------------------------------
__device__ __forceinline__ uint32_t smem_u32(const void* p) {
    return (uint32_t)__cvta_generic_to_shared(p);
}

__device__ __forceinline__ float block_reduce_sum(float v) {
    __shared__ float red[8];
    int lane = threadIdx.x & 31;
    int wid  = threadIdx.x >> 5;
    #pragma unroll
    for (int o = 16; o > 0; o >>= 1) v += __shfl_xor_sync(0xffffffffu, v, o);
    if (lane == 0) red[wid] = v;
    __syncthreads();
    if (wid == 0) {
        v = (lane < ((int)blockDim.x >> 5)) ? red[lane] : 0.0f;
        #pragma unroll
        for (int o = 4; o > 0; o >>= 1) v += __shfl_xor_sync(0xffffffffu, v, o);
    }
    return v;
}

// ---------------------------------------------------------------------------
// K_NORMS: warp-per-row inv-norms (8 rows per 256-thread block) + zero block
#define NORM_BLOCKS 1024
#define NORMS_GRID  (NORM_BLOCKS + 1)

__global__ void k_norms(const float* __restrict__ X) {
    int b = blockIdx.x;
    int t = threadIdx.x;
    int lane = t & 31;
    int wid  = t >> 5;

    if (b < NORM_BLOCKS) {
        int row = b * 8 + wid;
        const float4* xr = (const float4*)&X[(size_t)row * DD];
        float4 v0 = xr[lane * 2];
        float4 v1 = xr[lane * 2 + 1];
        float ss = v0.x * v0.x + v0.y * v0.y + v0.z * v0.z + v0.w * v0.w
                 + v1.x * v1.x + v1.y * v1.y + v1.z * v1.z + v1.w * v1.w;
        #pragma unroll
        for (int o = 16; o > 0; o >>= 1) ss += __shfl_xor_sync(0xffffffffu, ss, o);
        if (lane == 0) g_inorm[row] = 1.0f / fmaxf(sqrtf(ss), 1e-8f);
    } else {
        if (t < 2) g_acc[t] = 0.0;
        if (t == 2) g_done = 0u;
    }
}

// ---------------------------------------------------------------------------
// K_PREP_T: 64x64-tile transposes into Mt (scalar smem stores: 65-float rows)
#define XT_BLOCKS 512
#define PT_BLOCKS 256
#define PREPT_GRID (XT_BLOCKS + PT_BLOCKS)

__global__ void k_prep_t(const float* __restrict__ X, const float* __restrict__ Pr) {
    __shared__ float tt[64][65];
    __shared__ float sI[64];

    int b = blockIdx.x;
    int t = threadIdx.x;
    int tx = t & 15, ty = t >> 4;

    if (b < XT_BLOCKS) {
        int kb = (b >> 2) * 64;
        int db = (b & 3) * 64;
        #pragma unroll
        for (int r = ty; r < 64; r += 16) {
            float4 v = *(const float4*)&X[(size_t)(kb + r) * DD + db + tx * 4];
            tt[r][tx * 4 + 0] = v.x;
            tt[r][tx * 4 + 1] = v.y;
            tt[r][tx * 4 + 2] = v.z;
            tt[r][tx * 4 + 3] = v.w;
        }
        if (t < 64) sI[t] = g_inorm[kb + t];
        __syncthreads();
        #pragma unroll
        for (int rr = ty; rr < 64; rr += 16) {
            int cc = tx * 4;
            float f0 = tt[cc + 0][rr] * sI[cc + 0];
            float f1 = tt[cc + 1][rr] * sI[cc + 1];
            float f2 = tt[cc + 2][rr] * sI[cc + 2];
            float f3 = tt[cc + 3][rr] * sI[cc + 3];
            __nv_bfloat162 lo = __floats2bfloat162_rn(f0, f1);
            __nv_bfloat162 hi = __floats2bfloat162_rn(f2, f3);
            uint2 o; o.x = *(uint32_t*)&lo; o.y = *(uint32_t*)&hi;
            *(uint2*)&g_Mt[(size_t)(128 + db + rr) * NN + kb + cc] = o;
        }
    } else {
        int b2 = b - XT_BLOCKS;
        int kb = (b2 >> 1) * 64;
        int pb = (b2 & 1) * 64;
        #pragma unroll
        for (int r = ty; r < 64; r += 16) {
            float4 v = *(const float4*)&Pr[(size_t)(kb + r) * PP + pb + tx * 4];
            tt[r][tx * 4 + 0] = v.x;
            tt[r][tx * 4 + 1] = v.y;
            tt[r][tx * 4 + 2] = v.z;
            tt[r][tx * 4 + 3] = v.w;
        }
        __syncthreads();
        #pragma unroll
        for (int rr = ty; rr < 64; rr += 16) {
            int cc = tx * 4;
            __nv_bfloat162 lo = __floats2bfloat162_rn(tt[cc + 0][rr], tt[cc + 1][rr]);
            __nv_bfloat162 hi = __floats2bfloat162_rn(tt[cc + 2][rr], tt[cc + 3][rr]);
            uint2 o; o.x = *(uint32_t*)&lo; o.y = *(uint32_t*)&hi;
            *(uint2*)&g_Mt[(size_t)(pb + rr) * NN + kb + cc] = o;
        }
    }
}

// ---------------------------------------------------------------------------
// MAIN: 128 structure CTAs + 18 gram CTAs, one wave. Double-buffered smem,
// one __syncthreads per K-tile, 32x32 warp tiles (2x4 warp grid).
#define STRUCT_BLOCKS 128
#define GRAM_BLOCKS 18
#define GRID_MAIN (STRUCT_BLOCKS + GRAM_BLOCKS)

#define KT 64
#define APAD 72
#define SA_STAGE (64 * APAD)     // bf16 elems per A stage
#define SB_STAGE (128 * APAD)    // bf16 elems per B stage
#define SMEM_MAIN ((SA_STAGE + SB_STAGE) * 2 * 2)   // bytes = 55296

__device__ __forceinline__ void ldmx4(uint32_t& r0, uint32_t& r1, uint32_t& r2,
                                      uint32_t& r3, uint32_t addr) {
    asm volatile("ldmatrix.sync.aligned.m8n8.x4.shared.b16 {%0,%1,%2,%3}, [%4];"
                 : "=r"(r0), "=r"(r1), "=r"(r2), "=r"(r3) : "r"(addr));
}
__device__ __forceinline__ void mma_bf16(float* c, uint32_t a0, uint32_t a1,
                                         uint32_t a2, uint32_t a3,
                                         uint32_t b0, uint32_t b1) {
    asm volatile(
        "mma.sync.aligned.m16n8k16.row.col.f32.bf16.bf16.f32 "
        "{%0,%1,%2,%3}, {%4,%5,%6,%7}, {%8,%9}, {%0,%1,%2,%3};"
        : "+f"(c[0]), "+f"(c[1]), "+f"(c[2]), "+f"(c[3])
        : "r"(a0), "r"(a1), "r"(a2), "r"(a3), "r"(b0), "r"(b1));
}

template <bool GRAM>
__device__ __forceinline__ void gemm_body(const float* __restrict__ Af32,
                                          const __nv_bfloat16* __restrict__ Abf,
                                          const __nv_bfloat16* __restrict__ Bbf,
                                          const float* __restrict__ Pr,
                                          const float* __restrict__ W,
                                          int r_base, int c_base,
                                          __nv_bfloat16* sAb, __nv_bfloat16* sBb) {
    int tid  = threadIdx.x;
    int wid  = tid >> 5;
    int lane = tid & 31;
    int gid  = lane >> 2;
    int tid4 = lane & 3;
    int wm   = wid >> 2;           // 0..1 : 32-row slice
    int wn   = wid & 3;            // 0..3 : 32-col slice

    int lrow = (lane & 7) + ((lane >> 3) & 1) * 8;
    int lk8  = (lane >> 4) * 8;

    uint32_t sA_u0 = smem_u32(sAb);
    uint32_t sB_u0 = smem_u32(sBb);

    float4 rA[4];
    uint4  rAg[2];
    uint4  rB[4];

    // ---- helpers (macros via lambdas) ----
    auto load_regs = [&](int it) {
        int k0 = it * KT;
        #pragma unroll
        for (int q = 0; q < 4; q++) {
            int c = tid + q * 256;
            if (!GRAM)
                rA[q] = *(const float4*)&Af32[(size_t)(c >> 4) * NN + k0 + (c & 15) * 4];
            rB[q] = *(const uint4*)&Bbf[(size_t)(c >> 3) * NN + k0 + (c & 7) * 8];
        }
        if (GRAM) {
            #pragma unroll
            for (int q = 0; q < 2; q++) {
                int c = tid + q * 256;
                rAg[q] = *(const uint4*)&Abf[(size_t)(c >> 3) * NN + k0 + (c & 7) * 8];
            }
        }
    };
    auto store_tile = [&](int buf) {
        __nv_bfloat16* sA = sAb + buf * SA_STAGE;
        __nv_bfloat16* sB = sBb + buf * SB_STAGE;
        if (!GRAM) {
            #pragma unroll
            for (int q = 0; q < 4; q++) {
                int c = tid + q * 256;
                __nv_bfloat162 lo = __floats2bfloat162_rn(rA[q].x, rA[q].y);
                __nv_bfloat162 hi = __floats2bfloat162_rn(rA[q].z, rA[q].w);
                uint2 o; o.x = *(uint32_t*)&lo; o.y = *(uint32_t*)&hi;
                *(uint2*)&sA[(c >> 4) * APAD + (c & 15) * 4] = o;
            }
        } else {
            #pragma unroll
            for (int q = 0; q < 2; q++) {
                int c = tid + q * 256;
                *(uint4*)&sA[(c >> 3) * APAD + (c & 7) * 8] = rAg[q];
            }
        }
        #pragma unroll
        for (int q = 0; q < 4; q++) {
            int c = tid + q * 256;
            *(uint4*)&sB[(c >> 3) * APAD + (c & 7) * 8] = rB[q];
        }
    };

    float acc[2][4][4] = {};

    const int NIT = NN / KT;   // 128

    load_regs(0);
    store_tile(0);
    load_regs(1);
    __syncthreads();

    for (int it = 0; it < NIT; it++) {
        if (it + 1 < NIT) store_tile((it + 1) & 1);   // regs hold tile it+1
        if (it + 2 < NIT) load_regs(it + 2);          // prefetch tile it+2

        uint32_t aU = sA_u0 + (it & 1) * (SA_STAGE * 2);
        uint32_t bU = sB_u0 + (it & 1) * (SB_STAGE * 2);

        #pragma unroll
        for (int kk = 0; kk < KT; kk += 16) {
            uint32_t a[2][4];
            ldmx4(a[0][0], a[0][1], a[0][2], a[0][3],
                  aU + ((wm * 32 + lrow) * APAD + kk + lk8) * 2);
            ldmx4(a[1][0], a[1][1], a[1][2], a[1][3],
                  aU + ((wm * 32 + 16 + lrow) * APAD + kk + lk8) * 2);
            #pragma unroll
            for (int nj = 0; nj < 2; nj++) {
                uint32_t b0, b1, b2, b3;
                ldmx4(b0, b1, b2, b3,
                      bU + ((wn * 32 + nj * 16 + lrow) * APAD + kk + lk8) * 2);
                mma_bf16(acc[0][nj * 2 + 0], a[0][0], a[0][1], a[0][2], a[0][3], b0, b2);
                mma_bf16(acc[0][nj * 2 + 1], a[0][0], a[0][1], a[0][2], a[0][3], b1, b3);
                mma_bf16(acc[1][nj * 2 + 0], a[1][0], a[1][1], a[1][2], a[1][3], b0, b2);
                mma_bf16(acc[1][nj * 2 + 1], a[1][0], a[1][1], a[1][2], a[1][3], b1, b3);
            }
        }
        __syncthreads();
    }

    // epilogue
    float s = 0.0f;
    #pragma unroll
    for (int mi = 0; mi < 2; mi++) {
        #pragma unroll
        for (int ni = 0; ni < 4; ni++) {
            int col = wn * 32 + ni * 8 + tid4 * 2;
            int m0  = wm * 32 + mi * 16 + gid;
            if (!GRAM) {
                int m = r_base + m0;
                float p00 = Pr[(size_t)m * PP + col];
                float p01 = Pr[(size_t)m * PP + col + 1];
                float p10 = Pr[(size_t)(m + 8) * PP + col];
                float p11 = Pr[(size_t)(m + 8) * PP + col + 1];
                float d0 = p00 - acc[mi][ni][0];
                float d1 = p01 - acc[mi][ni][1];
                float d2 = p10 - acc[mi][ni][2];
                float d3 = p11 - acc[mi][ni][3];
                s += d0 * d0 + d1 * d1 + d2 * d2 + d3 * d3;
                float w00 = W[(size_t)m * PP + col];
                float w01 = W[(size_t)m * PP + col + 1];
                float w10 = W[(size_t)(m + 8) * PP + col];
                float w11 = W[(size_t)(m + 8) * PP + col + 1];
                float e0 = p00 - w00, e1 = p01 - w01, e2 = p10 - w10, e3 = p11 - w11;
                s += e0 * e0 + e1 * e1 + e2 * e2 + e3 * e3;
            } else {
                int r0g = r_base + m0;
                int r1g = r0g + 8;
                int c0g = c_base + col;
                int c1g = c0g + 1;
                float s00 = ((r0g < 128) == (c0g < 128)) ? 1.0f : -1.0f;
                float s01 = ((r0g < 128) == (c1g < 128)) ? 1.0f : -1.0f;
                float s10 = ((r1g < 128) == (c0g < 128)) ? 1.0f : -1.0f;
                float s11 = ((r1g < 128) == (c1g < 128)) ? 1.0f : -1.0f;
                s += s00 * acc[mi][ni][0] * acc[mi][ni][0]
                   + s01 * acc[mi][ni][1] * acc[mi][ni][1]
                   + s10 * acc[mi][ni][2] * acc[mi][ni][2]
                   + s11 * acc[mi][ni][3] * acc[mi][ni][3];
            }
        }
    }
    s = block_reduce_sum(s);
    if (tid == 0) atomicAdd(&g_acc[GRAM ? 0 : 1], (double)s);
}

__global__ void __launch_bounds__(256) k_main(const float* __restrict__ A,
                                              const float* __restrict__ Pr,
                                              const float* __restrict__ W,
                                              float* __restrict__ out) {
    extern __shared__ __align__(16) char dynsm[];
    __nv_bfloat16* sAb = (__nv_bfloat16*)dynsm;
    __nv_bfloat16* sBb = (__nv_bfloat16*)(dynsm + SA_STAGE * 2 * 2);

    int bid = blockIdx.x;
    if (bid < STRUCT_BLOCKS) {
        gemm_body<false>(A + (size_t)bid * 64 * NN, nullptr, g_Mt, Pr, W,
                         bid * 64, 0, sAb, sBb);
    } else {
        int g = bid - STRUCT_BLOCKS;
        int rblk = g / 3, cblk = g % 3;
        gemm_body<true>(nullptr,
                        g_Mt + (size_t)(rblk * 64) * NN,
                        g_Mt + (size_t)(cblk * 128) * NN,
                        Pr, nullptr, rblk * 64, cblk * 128, sAb, sBb);
    }

    __shared__ unsigned int s_ticket;
    __threadfence();
    if (threadIdx.x == 0) s_ticket = atomicAdd(&g_done, 1u);
    __syncthreads();
    if (s_ticket == GRID_MAIN - 1) {
        if (threadIdx.x == 0) {
            double nn = (double)NN * (double)NN;
            double np = (double)NN * (double)PP;
            out[0] = (float)(g_acc[0] / nn + g_acc[1] / np);
            g_done = 0u;
        }
    }
}

// ---------------------------------------------------------------------------
extern "C" void kernel_launch(void* const* d_in, const int* in_sizes, int n_in,
                              void* d_out, int out_size) {
    const float* preds = (const float*)d_in[0];   // [8192, 128]
    const float* emb   = (const float*)d_in[1];   // [8192, 256]
    const float* adj   = (const float*)d_in[2];   // [8192, 8192]
    const float* wts   = (const float*)d_in[3];   // [8192, 128]
    float* out = (float*)d_out;

    // idempotent; not a stream op / not an allocation -> capture-safe
    cudaFuncSetAttribute(k_main, cudaFuncAttributeMaxDynamicSharedMemorySize, SMEM_MAIN);

    k_norms<<<NORMS_GRID, 256>>>(emb);
    k_prep_t<<<PREPT_GRID, 256>>>(emb, preds);
    k_main<<<GRID_MAIN, 256, SMEM_MAIN>>>(adj, preds, wts, out);
}

// round 11
// speedup vs baseline: 8.8109x; 1.0488x over previous
#include <cuda_runtime.h>
#include <cuda_bf16.h>
#include <math.h>
#include <stdint.h>

#define NN 8192
#define PP 128
#define DD 256

// ---------------- device scratch (static globals — no runtime alloc) ----------
__device__ __nv_bfloat16 g_Mt[384 * NN];            // Mᵀ bf16: rows 0-127 = Pᵀ, 128-383 = Xnᵀ
__device__ double g_acc[2];                         // 0: coherence, 1: structure+weight SSE
__device__ unsigned int g_done;                     // finisher ticket

// ---------------------------------------------------------------------------
__device__ __forceinline__ uint32_t smem_u32(const void* p) {
    return (uint32_t)__cvta_generic_to_shared(p);
}

// block reduce for up to 512 threads
__device__ __forceinline__ float block_reduce_sum(float v) {
    __shared__ float red[16];
    int lane = threadIdx.x & 31;
    int wid  = threadIdx.x >> 5;
    #pragma unroll
    for (int o = 16; o > 0; o >>= 1) v += __shfl_xor_sync(0xffffffffu, v, o);
    if (lane == 0) red[wid] = v;
    __syncthreads();
    if (wid == 0) {
        int nw = (int)blockDim.x >> 5;
        v = (lane < nw) ? red[lane] : 0.0f;
        #pragma unroll
        for (int o = 8; o > 0; o >>= 1) v += __shfl_xor_sync(0xffffffffu, v, o);
    }
    return v;
}

// ---------------------------------------------------------------------------
// K_PREP (fused, 256 threads):
//   blocks [0,128):    X slab 64 rows x 256 cols -> norms in-block -> 4 scaled
//                      transposed tiles into Mt rows 128..383
//   blocks [128,384):  P 64x64 transpose tiles into Mt rows 0..127
//   block  384:        zero accumulators
#define XSLAB_BLOCKS 128
#define PT_BLOCKS    256
#define PREP_GRID    (XSLAB_BLOCKS + PT_BLOCKS + 1)
#define XS 259                                     // X slab smem row stride (floats)
#define SMEM_PREP (64 * XS * 4 + 64 * 4)           // 66560 bytes

__global__ void __launch_bounds__(256) k_prep(const float* __restrict__ X,
                                              const float* __restrict__ Pr) {
    extern __shared__ __align__(16) char dynsm[];
    int b = blockIdx.x;
    int t = threadIdx.x;
    int lane = t & 31;
    int wrp  = t >> 5;
    int tx = t & 15, ty = t >> 4;

    if (b < XSLAB_BLOCKS) {
        float* tt = (float*)dynsm;                 // [64][XS]
        float* sI = (float*)(dynsm + 64 * XS * 4); // [64]
        int kb = b * 64;                            // source row base (n)

        // phase 1: load 64x256 slab (float4 gmem, scalar smem)
        #pragma unroll
        for (int q = 0; q < 16; q++) {
            int c = t + q * 256;
            int row = c >> 6;
            int col = (c & 63) * 4;
            float4 v = *(const float4*)&X[(size_t)(kb + row) * DD + col];
            tt[row * XS + col + 0] = v.x;
            tt[row * XS + col + 1] = v.y;
            tt[row * XS + col + 2] = v.z;
            tt[row * XS + col + 3] = v.w;
        }
        __syncthreads();

        // phase 2: per-row inv norms (warp per 8 rows)
        #pragma unroll
        for (int r8 = 0; r8 < 8; r8++) {
            int row = wrp * 8 + r8;
            float ss = 0.0f;
            #pragma unroll
            for (int j = 0; j < 8; j++) {
                float x = tt[row * XS + lane * 8 + j];
                ss += x * x;
            }
            #pragma unroll
            for (int o = 16; o > 0; o >>= 1) ss += __shfl_xor_sync(0xffffffffu, ss, o);
            if (lane == 0) sI[row] = 1.0f / fmaxf(sqrtf(ss), 1e-8f);
        }
        __syncthreads();

        // phase 3: 4 transposed scaled tiles -> Mt rows 128..383
        #pragma unroll
        for (int dt = 0; dt < 4; dt++) {
            #pragma unroll
            for (int rr = ty; rr < 64; rr += 16) {
                int cc = tx * 4;
                int sc = dt * 64 + rr;             // source col = Mt row offset
                float f0 = tt[(cc + 0) * XS + sc] * sI[cc + 0];
                float f1 = tt[(cc + 1) * XS + sc] * sI[cc + 1];
                float f2 = tt[(cc + 2) * XS + sc] * sI[cc + 2];
                float f3 = tt[(cc + 3) * XS + sc] * sI[cc + 3];
                __nv_bfloat162 lo = __floats2bfloat162_rn(f0, f1);
                __nv_bfloat162 hi = __floats2bfloat162_rn(f2, f3);
                uint2 o; o.x = *(uint32_t*)&lo; o.y = *(uint32_t*)&hi;
                *(uint2*)&g_Mt[(size_t)(128 + dt * 64 + rr) * NN + kb + cc] = o;
            }
        }
    } else if (b < XSLAB_BLOCKS + PT_BLOCKS) {
        float (*tt65)[65] = (float(*)[65])dynsm;
        int b2 = b - XSLAB_BLOCKS;
        int kb = (b2 >> 1) * 64;
        int pb = (b2 & 1) * 64;
        #pragma unroll
        for (int r = ty; r < 64; r += 16) {
            float4 v = *(const float4*)&Pr[(size_t)(kb + r) * PP + pb + tx * 4];
            tt65[r][tx * 4 + 0] = v.x;
            tt65[r][tx * 4 + 1] = v.y;
            tt65[r][tx * 4 + 2] = v.z;
            tt65[r][tx * 4 + 3] = v.w;
        }
        __syncthreads();
        #pragma unroll
        for (int rr = ty; rr < 64; rr += 16) {
            int cc = tx * 4;
            __nv_bfloat162 lo = __floats2bfloat162_rn(tt65[cc + 0][rr], tt65[cc + 1][rr]);
            __nv_bfloat162 hi = __floats2bfloat162_rn(tt65[cc + 2][rr], tt65[cc + 3][rr]);
            uint2 o; o.x = *(uint32_t*)&lo; o.y = *(uint32_t*)&hi;
            *(uint2*)&g_Mt[(size_t)(pb + rr) * NN + kb + cc] = o;
        }
    } else {
        if (t < 2) g_acc[t] = 0.0;
        if (t == 2) g_done = 0u;
    }
}

// ---------------------------------------------------------------------------
// MAIN: 128 structure CTAs + 18 gram CTAs, one wave. 512 threads (16 warps,
// 4/SMSP), warp tile 16x32, double-buffered smem, one barrier per K-tile.
#define STRUCT_BLOCKS 128
#define GRAM_BLOCKS 18
#define GRID_MAIN (STRUCT_BLOCKS + GRAM_BLOCKS)

#define KT 64
#define APAD 72
#define SA_STAGE (64 * APAD)
#define SB_STAGE (128 * APAD)
#define SMEM_MAIN ((SA_STAGE + SB_STAGE) * 2 * 2)   // 55296 bytes

__device__ __forceinline__ void ldmx4(uint32_t& r0, uint32_t& r1, uint32_t& r2,
                                      uint32_t& r3, uint32_t addr) {
    asm volatile("ldmatrix.sync.aligned.m8n8.x4.shared.b16 {%0,%1,%2,%3}, [%4];"
                 : "=r"(r0), "=r"(r1), "=r"(r2), "=r"(r3) : "r"(addr));
}
__device__ __forceinline__ void mma_bf16(float* c, uint32_t a0, uint32_t a1,
                                         uint32_t a2, uint32_t a3,
                                         uint32_t b0, uint32_t b1) {
    asm volatile(
        "mma.sync.aligned.m16n8k16.row.col.f32.bf16.bf16.f32 "
        "{%0,%1,%2,%3}, {%4,%5,%6,%7}, {%8,%9}, {%0,%1,%2,%3};"
        : "+f"(c[0]), "+f"(c[1]), "+f"(c[2]), "+f"(c[3])
        : "r"(a0), "r"(a1), "r"(a2), "r"(a3), "r"(b0), "r"(b1));
}

template <bool GRAM>
__device__ __forceinline__ void gemm_body(const float* __restrict__ Af32,
                                          const __nv_bfloat16* __restrict__ Abf,
                                          const __nv_bfloat16* __restrict__ Bbf,
                                          const float* __restrict__ Pr,
                                          const float* __restrict__ W,
                                          int r_base, int c_base,
                                          __nv_bfloat16* sAb, __nv_bfloat16* sBb) {
    int tid  = threadIdx.x;             // 0..511
    int wid  = tid >> 5;                // 0..15
    int lane = tid & 31;
    int gid  = lane >> 2;
    int tid4 = lane & 3;
    int wm   = wid >> 2;                // 0..3 : 16-row slice
    int wn   = wid & 3;                 // 0..3 : 32-col slice

    int lrow = (lane & 7) + ((lane >> 3) & 1) * 8;
    int lk8  = (lane >> 4) * 8;

    uint32_t sA_u0 = smem_u32(sAb);
    uint32_t sB_u0 = smem_u32(sBb);

    float4 rA[2];
    uint4  rAg;
    uint4  rB[2];

    auto load_regs = [&](int it) {
        int k0 = it * KT;
        #pragma unroll
        for (int q = 0; q < 2; q++) {
            int c = tid + q * 512;
            if (!GRAM)
                rA[q] = *(const float4*)&Af32[(size_t)(c >> 4) * NN + k0 + (c & 15) * 4];
            rB[q] = *(const uint4*)&Bbf[(size_t)(c >> 3) * NN + k0 + (c & 7) * 8];
        }
        if (GRAM)
            rAg = *(const uint4*)&Abf[(size_t)(tid >> 3) * NN + k0 + (tid & 7) * 8];
    };
    auto store_tile = [&](int buf) {
        __nv_bfloat16* sA = sAb + buf * SA_STAGE;
        __nv_bfloat16* sB = sBb + buf * SB_STAGE;
        if (!GRAM) {
            #pragma unroll
            for (int q = 0; q < 2; q++) {
                int c = tid + q * 512;
                __nv_bfloat162 lo = __floats2bfloat162_rn(rA[q].x, rA[q].y);
                __nv_bfloat162 hi = __floats2bfloat162_rn(rA[q].z, rA[q].w);
                uint2 o; o.x = *(uint32_t*)&lo; o.y = *(uint32_t*)&hi;
                *(uint2*)&sA[(c >> 4) * APAD + (c & 15) * 4] = o;
            }
        } else {
            *(uint4*)&sA[(tid >> 3) * APAD + (tid & 7) * 8] = rAg;
        }
        #pragma unroll
        for (int q = 0; q < 2; q++) {
            int c = tid + q * 512;
            *(uint4*)&sB[(c >> 3) * APAD + (c & 7) * 8] = rB[q];
        }
    };

    float acc[4][4] = {};

    const int NIT = NN / KT;   // 128

    load_regs(0);
    store_tile(0);
    load_regs(1);
    __syncthreads();

    for (int it = 0; it < NIT; it++) {
        if (it + 1 < NIT) store_tile((it + 1) & 1);
        if (it + 2 < NIT) load_regs(it + 2);

        uint32_t aU = sA_u0 + (it & 1) * (SA_STAGE * 2);
        uint32_t bU = sB_u0 + (it & 1) * (SB_STAGE * 2);

        #pragma unroll
        for (int kk = 0; kk < KT; kk += 16) {
            uint32_t a0, a1, a2, a3;
            ldmx4(a0, a1, a2, a3,
                  aU + ((wm * 16 + lrow) * APAD + kk + lk8) * 2);
            #pragma unroll
            for (int nj = 0; nj < 2; nj++) {
                uint32_t b0, b1, b2, b3;
                ldmx4(b0, b1, b2, b3,
                      bU + ((wn * 32 + nj * 16 + lrow) * APAD + kk + lk8) * 2);
                mma_bf16(acc[nj * 2 + 0], a0, a1, a2, a3, b0, b2);
                mma_bf16(acc[nj * 2 + 1], a0, a1, a2, a3, b1, b3);
            }
        }
        __syncthreads();
    }

    // epilogue
    float s = 0.0f;
    #pragma unroll
    for (int ni = 0; ni < 4; ni++) {
        int col = wn * 32 + ni * 8 + tid4 * 2;
        int m0  = wm * 16 + gid;
        if (!GRAM) {
            int m = r_base + m0;
            float p00 = Pr[(size_t)m * PP + col];
            float p01 = Pr[(size_t)m * PP + col + 1];
            float p10 = Pr[(size_t)(m + 8) * PP + col];
            float p11 = Pr[(size_t)(m + 8) * PP + col + 1];
            float d0 = p00 - acc[ni][0];
            float d1 = p01 - acc[ni][1];
            float d2 = p10 - acc[ni][2];
            float d3 = p11 - acc[ni][3];
            s += d0 * d0 + d1 * d1 + d2 * d2 + d3 * d3;
            float w00 = W[(size_t)m * PP + col];
            float w01 = W[(size_t)m * PP + col + 1];
            float w10 = W[(size_t)(m + 8) * PP + col];
            float w11 = W[(size_t)(m + 8) * PP + col + 1];
            float e0 = p00 - w00, e1 = p01 - w01, e2 = p10 - w10, e3 = p11 - w11;
            s += e0 * e0 + e1 * e1 + e2 * e2 + e3 * e3;
        } else {
            int r0g = r_base + m0;
            int r1g = r0g + 8;
            int c0g = c_base + col;
            int c1g = c0g + 1;
            float s00 = ((r0g < 128) == (c0g < 128)) ? 1.0f : -1.0f;
            float s01 = ((r0g < 128) == (c1g < 128)) ? 1.0f : -1.0f;
            float s10 = ((r1g < 128) == (c0g < 128)) ? 1.0f : -1.0f;
            float s11 = ((r1g < 128) == (c1g < 128)) ? 1.0f : -1.0f;
            s += s00 * acc[ni][0] * acc[ni][0] + s01 * acc[ni][1] * acc[ni][1]
               + s10 * acc[ni][2] * acc[ni][2] + s11 * acc[ni][3] * acc[ni][3];
        }
    }
    s = block_reduce_sum(s);
    if (tid == 0) atomicAdd(&g_acc[GRAM ? 0 : 1], (double)s);
}

__global__ void __launch_bounds__(512) k_main(const float* __restrict__ A,
                                              const float* __restrict__ Pr,
                                              const float* __restrict__ W,
                                              float* __restrict__ out) {
    extern __shared__ __align__(16) char dynsm[];
    __nv_bfloat16* sAb = (__nv_bfloat16*)dynsm;
    __nv_bfloat16* sBb = (__nv_bfloat16*)(dynsm + SA_STAGE * 2 * 2);

    int bid = blockIdx.x;
    if (bid < STRUCT_BLOCKS) {
        gemm_body<false>(A + (size_t)bid * 64 * NN, nullptr, g_Mt, Pr, W,
                         bid * 64, 0, sAb, sBb);
    } else {
        int g = bid - STRUCT_BLOCKS;
        int rblk = g / 3, cblk = g % 3;
        gemm_body<true>(nullptr,
                        g_Mt + (size_t)(rblk * 64) * NN,
                        g_Mt + (size_t)(cblk * 128) * NN,
                        Pr, nullptr, rblk * 64, cblk * 128, sAb, sBb);
    }

    __shared__ unsigned int s_ticket;
    __threadfence();
    if (threadIdx.x == 0) s_ticket = atomicAdd(&g_done, 1u);
    __syncthreads();
    if (s_ticket == GRID_MAIN - 1) {
        if (threadIdx.x == 0) {
            double nn = (double)NN * (double)NN;
            double np = (double)NN * (double)PP;
            out[0] = (float)(g_acc[0] / nn + g_acc[1] / np);
            g_done = 0u;
        }
    }
}

// ---------------------------------------------------------------------------
extern "C" void kernel_launch(void* const* d_in, const int* in_sizes, int n_in,
                              void* d_out, int out_size) {
    const float* preds = (const float*)d_in[0];   // [8192, 128]
    const float* emb   = (const float*)d_in[1];   // [8192, 256]
    const float* adj   = (const float*)d_in[2];   // [8192, 8192]
    const float* wts   = (const float*)d_in[3];   // [8192, 128]
    float* out = (float*)d_out;

    // idempotent; capture-safe (no alloc, no sync)
    cudaFuncSetAttribute(k_prep, cudaFuncAttributeMaxDynamicSharedMemorySize, SMEM_PREP);
    cudaFuncSetAttribute(k_main, cudaFuncAttributeMaxDynamicSharedMemorySize, SMEM_MAIN);

    k_prep<<<PREP_GRID, 256, SMEM_PREP>>>(emb, preds);
    k_main<<<GRID_MAIN, 512, SMEM_MAIN>>>(adj, preds, wts, out);
}